// round 6
// baseline (speedup 1.0000x reference)
#include <cuda_runtime.h>

#define INP   768
#define HID   768
#define NH    8
#define HD    96
#define UPD   1536
#define FOUT  3088
#define BATCH 8
#define SEQ   1024
#define ROWS  (BATCH*SEQ)   /* 8192 */
#define CAPV  15.0f

// -------------------- scratch (no allocs allowed) --------------------
__device__ float g_xn   [ (size_t)ROWS*INP ];
__device__ float g_xt   [ (size_t)ROWS*UPD ];
__device__ float g_rt   [ (size_t)ROWS*HID ];
__device__ float g_xc   [ (size_t)ROWS*UPD ];
__device__ float g_xskip[ (size_t)ROWS*HID ];
__device__ float g_fused[ (size_t)ROWS*FOUT ];
__device__ float g_ht   [ (size_t)ROWS*HID ];
__device__ float g_hn2  [ (size_t)ROWS*HID ];
__device__ float g_y1   [ (size_t)ROWS*HID ];

// -------------------- helpers --------------------
__device__ __forceinline__ void block_reduce_sum2(float& s, float& s2,
                                                  float* sh, float* sh2) {
    int lane = threadIdx.x & 31, wid = threadIdx.x >> 5;
#pragma unroll
    for (int o = 16; o > 0; o >>= 1) {
        s  += __shfl_xor_sync(0xffffffffu, s,  o);
        s2 += __shfl_xor_sync(0xffffffffu, s2, o);
    }
    if (lane == 0) { sh[wid] = s; sh2[wid] = s2; }
    __syncthreads();
    float t = 0.f, t2 = 0.f;
#pragma unroll
    for (int i = 0; i < 8; i++) { t += sh[i]; t2 += sh2[i]; }
    s = t; s2 = t2;
}

// -------------------- LayerNorm over 768 (one row per block) --------------------
__global__ __launch_bounds__(256) void ln1_kernel(const float* __restrict__ x,
                                                  const float* __restrict__ g,
                                                  const float* __restrict__ b,
                                                  float* __restrict__ y) {
    __shared__ float sh[8], sh2[8];
    int row = blockIdx.x, t = threadIdx.x;
    const float* xr = x + (size_t)row * INP;
    float* yr = y + (size_t)row * INP;
    float v0 = xr[t], v1 = xr[t + 256], v2 = xr[t + 512];
    float s = v0 + v1 + v2;
    float s2 = v0 * v0 + v1 * v1 + v2 * v2;
    block_reduce_sum2(s, s2, sh, sh2);
    float mean = s * (1.0f / INP);
    float var  = s2 * (1.0f / INP) - mean * mean;
    float r = rsqrtf(var + 1e-6f);
    yr[t]       = (v0 - mean) * r * g[t]       + b[t];
    yr[t + 256] = (v1 - mean) * r * g[t + 256] + b[t + 256];
    yr[t + 512] = (v2 - mean) * r * g[t + 512] + b[t + 512];
}

// -------------------- SGEMM NT: C[M,N] = A[M,K] * B[N,K]^T (+bias[n]) --------------------
// M multiple of 128, K multiple of 16; N guarded (3088 case).
__global__ __launch_bounds__(256) void sgemm_nt_kernel(
    int M, int N, int K,
    const float* __restrict__ A, const float* __restrict__ B,
    const float* __restrict__ bias, float* __restrict__ C) {
    __shared__ float As[16][128];
    __shared__ float Bs[16][128];
    int tid = threadIdx.x;
    int bm = blockIdx.y * 128;
    int bn = blockIdx.x * 128;
    int tx = tid & 15, ty = tid >> 4;
    int lrow = tid >> 2;            // 0..63
    int lcol = (tid & 3) << 2;      // 0,4,8,12

    const float* Abase = A + (size_t)(bm + lrow) * K + lcol;
    int br0 = bn + lrow, br1 = bn + lrow + 64;
    const float* Bbase0 = B + (size_t)br0 * K + lcol;
    const float* Bbase1 = B + (size_t)br1 * K + lcol;
    bool bv0 = br0 < N, bv1 = br1 < N;

    float acc[8][8];
#pragma unroll
    for (int i = 0; i < 8; i++)
#pragma unroll
        for (int j = 0; j < 8; j++) acc[i][j] = 0.f;

    const float4 z4 = make_float4(0.f, 0.f, 0.f, 0.f);
    for (int kt = 0; kt < K; kt += 16) {
        float4 a0 = *(const float4*)(Abase + kt);
        float4 a1 = *(const float4*)(Abase + (size_t)64 * K + kt);
        float4 b0 = bv0 ? *(const float4*)(Bbase0 + kt) : z4;
        float4 b1 = bv1 ? *(const float4*)(Bbase1 + kt) : z4;

        As[lcol + 0][lrow] = a0.x; As[lcol + 1][lrow] = a0.y;
        As[lcol + 2][lrow] = a0.z; As[lcol + 3][lrow] = a0.w;
        As[lcol + 0][lrow + 64] = a1.x; As[lcol + 1][lrow + 64] = a1.y;
        As[lcol + 2][lrow + 64] = a1.z; As[lcol + 3][lrow + 64] = a1.w;
        Bs[lcol + 0][lrow] = b0.x; Bs[lcol + 1][lrow] = b0.y;
        Bs[lcol + 2][lrow] = b0.z; Bs[lcol + 3][lrow] = b0.w;
        Bs[lcol + 0][lrow + 64] = b1.x; Bs[lcol + 1][lrow + 64] = b1.y;
        Bs[lcol + 2][lrow + 64] = b1.z; Bs[lcol + 3][lrow + 64] = b1.w;
        __syncthreads();

#pragma unroll
        for (int kk = 0; kk < 16; kk++) {
            float4 av0 = *(const float4*)(&As[kk][ty * 8]);
            float4 av1 = *(const float4*)(&As[kk][ty * 8 + 4]);
            float4 bw0 = *(const float4*)(&Bs[kk][tx * 8]);
            float4 bw1 = *(const float4*)(&Bs[kk][tx * 8 + 4]);
            float ar[8] = {av0.x, av0.y, av0.z, av0.w, av1.x, av1.y, av1.z, av1.w};
            float br[8] = {bw0.x, bw0.y, bw0.z, bw0.w, bw1.x, bw1.y, bw1.z, bw1.w};
#pragma unroll
            for (int i = 0; i < 8; i++)
#pragma unroll
                for (int j = 0; j < 8; j++)
                    acc[i][j] = fmaf(ar[i], br[j], acc[i][j]);
        }
        __syncthreads();
    }

#pragma unroll
    for (int i = 0; i < 8; i++) {
        int row = bm + ty * 8 + i;
        float* Crow = C + (size_t)row * N;
#pragma unroll
        for (int j = 0; j < 8; j += 4) {
            int n = bn + tx * 8 + j;
            if (n < N) {   // N%4==0 so whole float4 valid
                float4 v = make_float4(acc[i][j], acc[i][j + 1], acc[i][j + 2], acc[i][j + 3]);
                if (bias) {
                    v.x += bias[n]; v.y += bias[n + 1];
                    v.z += bias[n + 2]; v.w += bias[n + 3];
                }
                *(float4*)(Crow + n) = v;
            }
        }
    }
}

// -------------------- causal 4-tap feature conv + silu --------------------
__global__ void conv_silu_kernel(const float* __restrict__ xt,
                                 const float* __restrict__ w,
                                 float* __restrict__ xc) {
    int i = blockIdx.x * blockDim.x + threadIdx.x;
    if (i >= ROWS * UPD) return;
    int j = i % UPD;
    float acc = w[3] * xt[i];
    if (j >= 1) acc += w[2] * xt[i - 1];
    if (j >= 2) acc += w[1] * xt[i - 2];
    if (j >= 3) acc += w[0] * xt[i - 3];
    xc[i] = acc / (1.0f + expf(-acc));   // silu
}

// -------------------- sequential mLSTM scan: one block per (b,h) --------------------
// fused row layout: i[0:8) f[8:16) o[16:784) q[784:1552) k[1552:2320) v[2320:3088)
__global__ __launch_bounds__(96) void scan_kernel(const float* __restrict__ fused,
                                                  float* __restrict__ ht,
                                                  float* __restrict__ outC,
                                                  float* __restrict__ outN,
                                                  float* __restrict__ outM) {
    int bh = blockIdx.x, b = bh >> 3, h = bh & 7;
    int d = threadIdx.x;          // 0..95  (row of C)
    const float inv = rsqrtf((float)HD);

    float C[HD];
#pragma unroll
    for (int e = 0; e < HD; e++) C[e] = 0.f;
    float nd = 1.0f, m = 0.0f;

    __shared__ float qs[HD], ks[HD];
    __shared__ float wsum[3];

    size_t rb = (size_t)b * SEQ * FOUT;
    float qv = fused[rb + 784  + h * HD + d];
    float kv = fused[rb + 1552 + h * HD + d];
    float vv = fused[rb + 2320 + h * HD + d];
    float iv = fused[rb + h];
    float fv = fused[rb + 8 + h];

    for (int s = 0; s < SEQ; s++) {
        float qd = qv, kd = kv * inv, vd = vv;
        float i_t = CAPV * tanhf(iv * (1.0f / CAPV));
        float f_t = CAPV * tanhf(fv * (1.0f / CAPV));
        qs[d] = qd; ks[d] = kd;
        __syncthreads();

        // prefetch next step while computing this one
        if (s + 1 < SEQ) {
            size_t rb2 = ((size_t)b * SEQ + s + 1) * FOUT;
            qv = fused[rb2 + 784  + h * HD + d];
            kv = fused[rb2 + 1552 + h * HD + d];
            vv = fused[rb2 + 2320 + h * HD + d];
            iv = fused[rb2 + h];
            fv = fused[rb2 + 8 + h];
        }

        float m_t = fmaxf(f_t + m, i_t);
        float ie = expf(i_t - m_t);
        float fe = expf(f_t - m_t + m);
        m = m_t;

        float a = ie * vd;
        float hn0 = 0.f, hn1 = 0.f, hn2v = 0.f, hn3 = 0.f;
#pragma unroll
        for (int e = 0; e < HD; e += 4) {
            float c;
            c = fmaf(a, ks[e],     fe * C[e]);     C[e]     = c; hn0  = fmaf(c, qs[e],     hn0);
            c = fmaf(a, ks[e + 1], fe * C[e + 1]); C[e + 1] = c; hn1  = fmaf(c, qs[e + 1], hn1);
            c = fmaf(a, ks[e + 2], fe * C[e + 2]); C[e + 2] = c; hn2v = fmaf(c, qs[e + 2], hn2v);
            c = fmaf(a, ks[e + 3], fe * C[e + 3]); C[e + 3] = c; hn3  = fmaf(c, qs[e + 3], hn3);
        }
        float hn = (hn0 + hn1) + (hn2v + hn3);

        nd = fmaf(ie, kd, fe * nd);
        float dp = nd * qd;
#pragma unroll
        for (int o = 16; o > 0; o >>= 1) dp += __shfl_xor_sync(0xffffffffu, dp, o);
        if ((d & 31) == 0) wsum[d >> 5] = dp;
        __syncthreads();
        float den = fmaxf(wsum[0] + wsum[1] + wsum[2], 1.0f);

        ht[((size_t)b * SEQ + s) * HID + h * HD + d] = hn / den;
    }

    // final state outputs
    float* Cr = outC + ((size_t)bh * HD + d) * HD;
#pragma unroll
    for (int e = 0; e < HD; e++) Cr[e] = C[e];
    outN[bh * HD + d] = nd;
    if (d == 0) outM[bh] = m;
}

// -------------------- o-gate * h, then LayerNorm over 768 --------------------
__global__ __launch_bounds__(256) void post_kernel(const float* __restrict__ fused,
                                                   const float* __restrict__ ht,
                                                   const float* __restrict__ g,
                                                   const float* __restrict__ b,
                                                   float* __restrict__ y) {
    __shared__ float sh[8], sh2[8];
    int row = blockIdx.x, t = threadIdx.x;
    const float* fr = fused + (size_t)row * FOUT + 16;
    const float* hr = ht + (size_t)row * HID;
    float hv[3]; float s = 0.f, s2 = 0.f;
#pragma unroll
    for (int k = 0; k < 3; k++) {
        int j = t + k * 256;
        float oraw = fr[j];
        float o = 1.0f / (1.0f + expf(-CAPV * tanhf(oraw * (1.0f / CAPV))));
        float h = o * hr[j];
        hv[k] = h; s += h; s2 += h * h;
    }
    block_reduce_sum2(s, s2, sh, sh2);
    float mean = s * (1.0f / HID);
    float var  = s2 * (1.0f / HID) - mean * mean;
    float r = rsqrtf(var + 1e-6f);
    float* yr = y + (size_t)row * HID;
#pragma unroll
    for (int k = 0; k < 3; k++) {
        int j = t + k * 256;
        yr[j] = (hv[k] - mean) * r * g[j] + b[j];
    }
}

// -------------------- final fuse: (y1 + xskip)*silu(rt) + x --------------------
__global__ void final_kernel(const float* __restrict__ y1,
                             const float* __restrict__ xskip,
                             const float* __restrict__ rt,
                             const float* __restrict__ x,
                             float* __restrict__ out) {
    int i = blockIdx.x * blockDim.x + threadIdx.x;
    if (i >= ROWS * HID) return;
    float r = rt[i];
    float sil = r / (1.0f + expf(-r));
    out[i] = (y1[i] + xskip[i]) * sil + x[i];
}

// -------------------- launch --------------------
extern "C" void kernel_launch(void* const* d_in, const int* in_sizes, int n_in,
                              void* d_out, int out_size) {
    (void)in_sizes; (void)n_in; (void)out_size;
    const float* x       = (const float*)d_in[0];
    const float* ln1_g   = (const float*)d_in[1];
    const float* ln1_b   = (const float*)d_in[2];
    const float* W_up_l  = (const float*)d_in[3];
    const float* W_up_r  = (const float*)d_in[4];
    const float* conv_w  = (const float*)d_in[5];
    const float* W_skip  = (const float*)d_in[6];
    const float* fused_W = (const float*)d_in[7];
    const float* fused_b = (const float*)d_in[8];
    const float* ln2_g   = (const float*)d_in[9];
    const float* ln2_b   = (const float*)d_in[10];
    const float* W_down  = (const float*)d_in[11];
    float* out = (float*)d_out;

    float *xn, *xt, *rt, *xc, *xskip, *fused, *ht, *hn2, *y1;
    cudaGetSymbolAddress((void**)&xn,    g_xn);
    cudaGetSymbolAddress((void**)&xt,    g_xt);
    cudaGetSymbolAddress((void**)&rt,    g_rt);
    cudaGetSymbolAddress((void**)&xc,    g_xc);
    cudaGetSymbolAddress((void**)&xskip, g_xskip);
    cudaGetSymbolAddress((void**)&fused, g_fused);
    cudaGetSymbolAddress((void**)&ht,    g_ht);
    cudaGetSymbolAddress((void**)&hn2,   g_hn2);
    cudaGetSymbolAddress((void**)&y1,    g_y1);

    ln1_kernel<<<ROWS, 256>>>(x, ln1_g, ln1_b, xn);

    sgemm_nt_kernel<<<dim3(UPD / 128, ROWS / 128), 256>>>(ROWS, UPD, INP, xn, W_up_l, nullptr, xt);
    sgemm_nt_kernel<<<dim3(HID / 128, ROWS / 128), 256>>>(ROWS, HID, INP, xn, W_up_r, nullptr, rt);

    conv_silu_kernel<<<(ROWS * UPD + 255) / 256, 256>>>(xt, conv_w, xc);

    sgemm_nt_kernel<<<dim3(HID / 128, ROWS / 128), 256>>>(ROWS, HID, UPD, xc, W_skip, nullptr, xskip);
    sgemm_nt_kernel<<<dim3((FOUT + 127) / 128, ROWS / 128), 256>>>(ROWS, FOUT, UPD, xc, fused_W, fused_b, fused);

    float* outC = out + (size_t)ROWS * INP;
    float* outN = outC + (size_t)BATCH * NH * HD * HD;
    float* outM = outN + (size_t)BATCH * NH * HD;
    scan_kernel<<<BATCH * NH, 96>>>(fused, ht, outC, outN, outM);

    post_kernel<<<ROWS, 256>>>(fused, ht, ln2_g, ln2_b, hn2);

    sgemm_nt_kernel<<<dim3(HID / 128, ROWS / 128), 256>>>(ROWS, HID, HID, hn2, W_down, nullptr, y1);

    final_kernel<<<(ROWS * HID + 255) / 256, 256>>>(y1, xskip, rt, x, out);
}

// round 8
// speedup vs baseline: 1.0508x; 1.0508x over previous
#include <cuda_runtime.h>

#define INP   768
#define HID   768
#define NH    8
#define HD    96
#define UPD   1536
#define FOUT  3088
#define BATCH 8
#define SEQ   1024
#define ROWS  (BATCH*SEQ)   /* 8192 */
#define CAPV  15.0f

typedef unsigned long long ull;

// -------------------- scratch (no allocs allowed) --------------------
__device__ float g_xn   [ (size_t)ROWS*INP ];
__device__ float g_xt   [ (size_t)ROWS*UPD ];
__device__ float g_rt   [ (size_t)ROWS*HID ];
__device__ float g_xc   [ (size_t)ROWS*UPD ];
__device__ float g_xskip[ (size_t)ROWS*HID ];
__device__ float g_fused[ (size_t)ROWS*FOUT ];
__device__ float g_ht   [ (size_t)ROWS*HID ];
__device__ float g_dp   [ (size_t)ROWS*HID ];
__device__ float g_hn2  [ (size_t)ROWS*HID ];
__device__ float g_y1   [ (size_t)ROWS*HID ];

// -------------------- packed f32x2 helpers (Blackwell FFMA2 path) --------------------
__device__ __forceinline__ ull ffma2(ull a, ull b, ull c) {
    ull d; asm("fma.rn.f32x2 %0, %1, %2, %3;" : "=l"(d) : "l"(a), "l"(b), "l"(c)); return d;
}
__device__ __forceinline__ ull fmul2(ull a, ull b) {
    ull d; asm("mul.rn.f32x2 %0, %1, %2;" : "=l"(d) : "l"(a), "l"(b)); return d;
}
__device__ __forceinline__ ull fadd2(ull a, ull b) {
    ull d; asm("add.rn.f32x2 %0, %1, %2;" : "=l"(d) : "l"(a), "l"(b)); return d;
}
__device__ __forceinline__ ull bcast2(float x) {
    ull d; asm("mov.b64 %0, {%1, %1};" : "=l"(d) : "f"(x)); return d;
}
__device__ __forceinline__ float2 unpack2(ull v) {
    float2 f; asm("mov.b64 {%0, %1}, %2;" : "=f"(f.x), "=f"(f.y) : "l"(v)); return f;
}

// -------------------- helpers --------------------
__device__ __forceinline__ void block_reduce_sum2(float& s, float& s2,
                                                  float* sh, float* sh2) {
    int lane = threadIdx.x & 31, wid = threadIdx.x >> 5;
#pragma unroll
    for (int o = 16; o > 0; o >>= 1) {
        s  += __shfl_xor_sync(0xffffffffu, s,  o);
        s2 += __shfl_xor_sync(0xffffffffu, s2, o);
    }
    if (lane == 0) { sh[wid] = s; sh2[wid] = s2; }
    __syncthreads();
    float t = 0.f, t2 = 0.f;
#pragma unroll
    for (int i = 0; i < 8; i++) { t += sh[i]; t2 += sh2[i]; }
    s = t; s2 = t2;
}

// -------------------- LayerNorm over 768 (one row per block) --------------------
__global__ __launch_bounds__(256) void ln1_kernel(const float* __restrict__ x,
                                                  const float* __restrict__ g,
                                                  const float* __restrict__ b,
                                                  float* __restrict__ y) {
    __shared__ float sh[8], sh2[8];
    int row = blockIdx.x, t = threadIdx.x;
    const float* xr = x + (size_t)row * INP;
    float* yr = y + (size_t)row * INP;
    float v0 = xr[t], v1 = xr[t + 256], v2 = xr[t + 512];
    float s = v0 + v1 + v2;
    float s2 = v0 * v0 + v1 * v1 + v2 * v2;
    block_reduce_sum2(s, s2, sh, sh2);
    float mean = s * (1.0f / INP);
    float var  = s2 * (1.0f / INP) - mean * mean;
    float r = rsqrtf(var + 1e-6f);
    yr[t]       = (v0 - mean) * r * g[t]       + b[t];
    yr[t + 256] = (v1 - mean) * r * g[t + 256] + b[t + 256];
    yr[t + 512] = (v2 - mean) * r * g[t + 512] + b[t + 512];
}

// -------------------- FFMA2 SGEMM NT: C[M,N] = A[M,K]*B[N,K]^T (+bias) --------------------
// 128 threads; 128x128x16 tile; thread computes 16 rows x 8 cols as 8x8 packed-pair accs.
// M % 128 == 0, K % 16 == 0, N % 8 == 0 (col guard at float4x2 granularity).
__global__ __launch_bounds__(128) void sgemm2_nt_kernel(
    int M, int N, int K,
    const float* __restrict__ A, const float* __restrict__ B,
    const float* __restrict__ bias, float* __restrict__ Cout) {
    __shared__ float As[16][128];
    __shared__ float Bs[16][128];
    int tid = threadIdx.x;
    int bm = blockIdx.y * 128;
    int bn = blockIdx.x * 128;
    int tx = tid & 15, ty = tid >> 4;

    const float* Ap = A + (size_t)(bm + tid) * K;
    int brow = bn + tid;
    const float* Bp = B + (size_t)brow * K;
    bool bv = brow < N;

    ull acc[8][8];
#pragma unroll
    for (int p = 0; p < 8; p++)
#pragma unroll
        for (int j = 0; j < 8; j++) acc[p][j] = 0ull;

    const float4 z4 = make_float4(0.f, 0.f, 0.f, 0.f);
    float4 ra[4], rb[4];
#pragma unroll
    for (int q = 0; q < 4; q++) {
        ra[q] = *(const float4*)(Ap + q * 4);
        rb[q] = bv ? *(const float4*)(Bp + q * 4) : z4;
    }

    for (int kt = 0; kt < K; kt += 16) {
#pragma unroll
        for (int q = 0; q < 4; q++) {
            As[q * 4 + 0][tid] = ra[q].x; As[q * 4 + 1][tid] = ra[q].y;
            As[q * 4 + 2][tid] = ra[q].z; As[q * 4 + 3][tid] = ra[q].w;
            Bs[q * 4 + 0][tid] = rb[q].x; Bs[q * 4 + 1][tid] = rb[q].y;
            Bs[q * 4 + 2][tid] = rb[q].z; Bs[q * 4 + 3][tid] = rb[q].w;
        }
        __syncthreads();
        if (kt + 16 < K) {
#pragma unroll
            for (int q = 0; q < 4; q++) {
                ra[q] = *(const float4*)(Ap + kt + 16 + q * 4);
                rb[q] = bv ? *(const float4*)(Bp + kt + 16 + q * 4) : z4;
            }
        }
#pragma unroll
        for (int kk = 0; kk < 16; kk++) {
            // A pairs: rows (ty*16+2p, ty*16+2p+1) packed naturally
            ulonglong2 a01 = *(const ulonglong2*)&As[kk][ty * 16 + 0];
            ulonglong2 a23 = *(const ulonglong2*)&As[kk][ty * 16 + 4];
            ulonglong2 a45 = *(const ulonglong2*)&As[kk][ty * 16 + 8];
            ulonglong2 a67 = *(const ulonglong2*)&As[kk][ty * 16 + 12];
            ull pa[8] = {a01.x, a01.y, a23.x, a23.y, a45.x, a45.y, a67.x, a67.y};
            float4 b0 = *(const float4*)&Bs[kk][tx * 8];
            float4 b1 = *(const float4*)&Bs[kk][tx * 8 + 4];
            ull pb[8];
            pb[0] = bcast2(b0.x); pb[1] = bcast2(b0.y);
            pb[2] = bcast2(b0.z); pb[3] = bcast2(b0.w);
            pb[4] = bcast2(b1.x); pb[5] = bcast2(b1.y);
            pb[6] = bcast2(b1.z); pb[7] = bcast2(b1.w);
#pragma unroll
            for (int p = 0; p < 8; p++)
#pragma unroll
                for (int j = 0; j < 8; j++)
                    acc[p][j] = ffma2(pa[p], pb[j], acc[p][j]);
        }
        __syncthreads();
    }

    int cn = bn + tx * 8;
    if (cn < N) {
        float bb[8];
#pragma unroll
        for (int j = 0; j < 8; j++) bb[j] = bias ? bias[cn + j] : 0.f;
#pragma unroll
        for (int p = 0; p < 8; p++) {
            float2 f[8];
#pragma unroll
            for (int j = 0; j < 8; j++) f[j] = unpack2(acc[p][j]);
            int r0 = bm + ty * 16 + 2 * p;
            float* c0 = Cout + (size_t)r0 * N + cn;
            float* c1 = c0 + N;
            float4 v;
            v = make_float4(f[0].x + bb[0], f[1].x + bb[1], f[2].x + bb[2], f[3].x + bb[3]);
            *(float4*)c0 = v;
            v = make_float4(f[4].x + bb[4], f[5].x + bb[5], f[6].x + bb[6], f[7].x + bb[7]);
            *((float4*)c0 + 1) = v;
            v = make_float4(f[0].y + bb[0], f[1].y + bb[1], f[2].y + bb[2], f[3].y + bb[3]);
            *(float4*)c1 = v;
            v = make_float4(f[4].y + bb[4], f[5].y + bb[5], f[6].y + bb[6], f[7].y + bb[7]);
            *((float4*)c1 + 1) = v;
        }
    }
}

// -------------------- causal 4-tap feature conv + silu --------------------
__global__ void conv_silu_kernel(const float* __restrict__ xt,
                                 const float* __restrict__ w,
                                 float* __restrict__ xc) {
    int i = blockIdx.x * blockDim.x + threadIdx.x;
    if (i >= ROWS * UPD) return;
    int j = i % UPD;
    float acc = w[3] * xt[i];
    if (j >= 1) acc += w[2] * xt[i - 1];
    if (j >= 2) acc += w[1] * xt[i - 2];
    if (j >= 3) acc += w[0] * xt[i - 3];
    xc[i] = acc / (1.0f + expf(-acc));   // silu
}

// -------------------- sequential mLSTM scan: one block per (b,h) --------------------
// fused row layout: i[0:8) f[8:16) o[16:784) q[784:1552) k[1552:2320) v[2320:3088)
// Stores UNNORMALIZED hn and per-lane n*q partials; post_kernel reduces + divides.
__global__ __launch_bounds__(96) void scan_kernel(const float* __restrict__ fused,
                                                  float* __restrict__ ht,
                                                  float* __restrict__ dpo,
                                                  float* __restrict__ outC,
                                                  float* __restrict__ outN,
                                                  float* __restrict__ outM) {
    int bh = blockIdx.x, b = bh >> 3, h = bh & 7;
    int d = threadIdx.x;          // 0..95  (row of C)
    const float inv = rsqrtf((float)HD);

    ull C[48];                    // packed pairs over e
#pragma unroll
    for (int e = 0; e < 48; e++) C[e] = 0ull;
    float nd = 1.0f, m = 0.0f;

    __shared__ __align__(16) float qs[2][HD];
    __shared__ __align__(16) float ks[2][HD];

    size_t rb = (size_t)b * SEQ * FOUT;
    float qv = fused[rb + 784  + h * HD + d];
    float kv = fused[rb + 1552 + h * HD + d];
    float vv = fused[rb + 2320 + h * HD + d];
    float iv = fused[rb + h];
    float fv = fused[rb + 8 + h];

    for (int s = 0; s < SEQ; s++) {
        int p = s & 1;
        float qd = qv, kd = kv * inv, vd = vv;
        float i_t = CAPV * tanhf(iv * (1.0f / CAPV));
        float f_t = CAPV * tanhf(fv * (1.0f / CAPV));
        qs[p][d] = qd; ks[p][d] = kd;
        __syncthreads();

        // prefetch next step while computing this one
        if (s + 1 < SEQ) {
            size_t rb2 = ((size_t)b * SEQ + s + 1) * FOUT;
            qv = fused[rb2 + 784  + h * HD + d];
            kv = fused[rb2 + 1552 + h * HD + d];
            vv = fused[rb2 + 2320 + h * HD + d];
            iv = fused[rb2 + h];
            fv = fused[rb2 + 8 + h];
        }

        float m_t = fmaxf(f_t + m, i_t);
        float ie = expf(i_t - m_t);
        float fe = expf(f_t - m_t + m);
        m = m_t;

        ull pa  = bcast2(ie * vd);
        ull pfe = bcast2(fe);
        const ulonglong2* kp2 = (const ulonglong2*)ks[p];
        const ulonglong2* qp2 = (const ulonglong2*)qs[p];
        ull hn0 = 0ull, hn1 = 0ull, hn2a = 0ull, hn3 = 0ull;
#pragma unroll
        for (int e2 = 0; e2 < 24; e2 += 2) {
            ulonglong2 kk0 = kp2[e2],     qq0 = qp2[e2];
            ulonglong2 kk1 = kp2[e2 + 1], qq1 = qp2[e2 + 1];
            ull c;
            c = ffma2(pa, kk0.x, fmul2(pfe, C[2 * e2 + 0])); C[2 * e2 + 0] = c; hn0  = ffma2(c, qq0.x, hn0);
            c = ffma2(pa, kk0.y, fmul2(pfe, C[2 * e2 + 1])); C[2 * e2 + 1] = c; hn1  = ffma2(c, qq0.y, hn1);
            c = ffma2(pa, kk1.x, fmul2(pfe, C[2 * e2 + 2])); C[2 * e2 + 2] = c; hn2a = ffma2(c, qq1.x, hn2a);
            c = ffma2(pa, kk1.y, fmul2(pfe, C[2 * e2 + 3])); C[2 * e2 + 3] = c; hn3  = ffma2(c, qq1.y, hn3);
        }
        float2 hf = unpack2(fadd2(fadd2(hn0, hn1), fadd2(hn2a, hn3)));
        float hnv = hf.x + hf.y;

        nd = fmaf(ie, kd, fe * nd);
        size_t o = ((size_t)b * SEQ + s) * HID + h * HD + d;
        ht[o]  = hnv;          // unnormalized
        dpo[o] = nd * qd;      // denominator partial
    }

    // final state outputs
    float* Cr = outC + ((size_t)bh * HD + d) * HD;
#pragma unroll
    for (int e = 0; e < 48; e++) {
        float2 f = unpack2(C[e]);
        *(float2*)(Cr + 2 * e) = f;
    }
    outN[bh * HD + d] = nd;
    if (d == 0) outM[bh] = m;
}

// -------------------- denom reduce + o-gate * h/den, then LayerNorm over 768 --------------------
__global__ __launch_bounds__(256) void post_kernel(const float* __restrict__ fused,
                                                   const float* __restrict__ ht,
                                                   const float* __restrict__ dp,
                                                   const float* __restrict__ g,
                                                   const float* __restrict__ b,
                                                   float* __restrict__ y) {
    __shared__ float sh[8], sh2[8], sden[8];
    int row = blockIdx.x, t = threadIdx.x;
    int w = t >> 5, lane = t & 31;

    // warp w reduces denominator of head w (96 values)
    const float* dpr = dp + (size_t)row * HID;
    float sdp = dpr[w * 96 + lane] + dpr[w * 96 + 32 + lane] + dpr[w * 96 + 64 + lane];
#pragma unroll
    for (int o = 16; o > 0; o >>= 1) sdp += __shfl_xor_sync(0xffffffffu, sdp, o);
    if (lane == 0) sden[w] = fmaxf(sdp, 1.0f);
    __syncthreads();

    const float* fr = fused + (size_t)row * FOUT + 16;
    const float* hr = ht + (size_t)row * HID;
    float hv[3]; float s = 0.f, s2 = 0.f;
#pragma unroll
    for (int k = 0; k < 3; k++) {
        int j = t + k * 256;
        float oraw = fr[j];
        float og = 1.0f / (1.0f + expf(-CAPV * tanhf(oraw * (1.0f / CAPV))));
        float h = og * (hr[j] / sden[j / 96]);
        hv[k] = h; s += h; s2 += h * h;
    }
    block_reduce_sum2(s, s2, sh, sh2);
    float mean = s * (1.0f / HID);
    float var  = s2 * (1.0f / HID) - mean * mean;
    float r = rsqrtf(var + 1e-6f);
    float* yr = y + (size_t)row * HID;
#pragma unroll
    for (int k = 0; k < 3; k++) {
        int j = t + k * 256;
        yr[j] = (hv[k] - mean) * r * g[j] + b[j];
    }
}

// -------------------- final fuse: (y1 + xskip)*silu(rt) + x --------------------
__global__ void final_kernel(const float* __restrict__ y1,
                             const float* __restrict__ xskip,
                             const float* __restrict__ rt,
                             const float* __restrict__ x,
                             float* __restrict__ out) {
    int i = blockIdx.x * blockDim.x + threadIdx.x;
    if (i >= ROWS * HID) return;
    float r = rt[i];
    float sil = r / (1.0f + expf(-r));
    out[i] = (y1[i] + xskip[i]) * sil + x[i];
}

// -------------------- launch --------------------
extern "C" void kernel_launch(void* const* d_in, const int* in_sizes, int n_in,
                              void* d_out, int out_size) {
    (void)in_sizes; (void)n_in; (void)out_size;
    const float* x       = (const float*)d_in[0];
    const float* ln1_g   = (const float*)d_in[1];
    const float* ln1_b   = (const float*)d_in[2];
    const float* W_up_l  = (const float*)d_in[3];
    const float* W_up_r  = (const float*)d_in[4];
    const float* conv_w  = (const float*)d_in[5];
    const float* W_skip  = (const float*)d_in[6];
    const float* fused_W = (const float*)d_in[7];
    const float* fused_b = (const float*)d_in[8];
    const float* ln2_g   = (const float*)d_in[9];
    const float* ln2_b   = (const float*)d_in[10];
    const float* W_down  = (const float*)d_in[11];
    float* out = (float*)d_out;

    float *xn, *xt, *rt, *xc, *xskip, *fused, *ht, *dp, *hn2, *y1;
    cudaGetSymbolAddress((void**)&xn,    g_xn);
    cudaGetSymbolAddress((void**)&xt,    g_xt);
    cudaGetSymbolAddress((void**)&rt,    g_rt);
    cudaGetSymbolAddress((void**)&xc,    g_xc);
    cudaGetSymbolAddress((void**)&xskip, g_xskip);
    cudaGetSymbolAddress((void**)&fused, g_fused);
    cudaGetSymbolAddress((void**)&ht,    g_ht);
    cudaGetSymbolAddress((void**)&dp,    g_dp);
    cudaGetSymbolAddress((void**)&hn2,   g_hn2);
    cudaGetSymbolAddress((void**)&y1,    g_y1);

    ln1_kernel<<<ROWS, 256>>>(x, ln1_g, ln1_b, xn);

    sgemm2_nt_kernel<<<dim3(UPD / 128, ROWS / 128), 128>>>(ROWS, UPD, INP, xn, W_up_l, nullptr, xt);
    sgemm2_nt_kernel<<<dim3(HID / 128, ROWS / 128), 128>>>(ROWS, HID, INP, xn, W_up_r, nullptr, rt);

    conv_silu_kernel<<<(ROWS * UPD + 255) / 256, 256>>>(xt, conv_w, xc);

    sgemm2_nt_kernel<<<dim3(HID / 128, ROWS / 128), 128>>>(ROWS, HID, UPD, xc, W_skip, nullptr, xskip);
    sgemm2_nt_kernel<<<dim3((FOUT + 127) / 128, ROWS / 128), 128>>>(ROWS, FOUT, UPD, xc, fused_W, fused_b, fused);

    float* outC = out + (size_t)ROWS * INP;
    float* outN = outC + (size_t)BATCH * NH * HD * HD;
    float* outM = outN + (size_t)BATCH * NH * HD;
    scan_kernel<<<BATCH * NH, 96>>>(fused, ht, dp, outC, outN, outM);

    post_kernel<<<ROWS, 256>>>(fused, ht, dp, ln2_g, ln2_b, hn2);

    sgemm2_nt_kernel<<<dim3(HID / 128, ROWS / 128), 128>>>(ROWS, HID, HID, hn2, W_down, nullptr, y1);

    final_kernel<<<(ROWS * HID + 255) / 256, 256>>>(y1, xskip, rt, x, out);
}

// round 12
// speedup vs baseline: 2.0781x; 1.9776x over previous
#include <cuda_runtime.h>
#include <cuda_bf16.h>
#include <cstdint>

#define INP   768
#define HID   768
#define NH    8
#define HD    96
#define UPD   1536
#define FOUT  3088
#define BATCH 8
#define SEQ   1024
#define ROWS  (BATCH*SEQ)   /* 8192 */
#define CAPV  15.0f

typedef unsigned long long ull;

// -------------------- scratch (no allocs allowed) --------------------
// packed bf16 split buffers: A-pack = [hi | lo | hi] over 3K, B-pack = [hi | hi | lo]
__device__ __align__(256) __nv_bfloat16 g_xnP  [ (size_t)ROWS*3*INP ];
__device__ __align__(256) __nv_bfloat16 g_xcP  [ (size_t)ROWS*3*UPD ];
__device__ __align__(256) __nv_bfloat16 g_hn2P [ (size_t)ROWS*3*HID ];
__device__ __align__(256) __nv_bfloat16 g_WuplP[ (size_t)UPD*3*INP ];
__device__ __align__(256) __nv_bfloat16 g_WuprP[ (size_t)HID*3*INP ];
__device__ __align__(256) __nv_bfloat16 g_WskipP[(size_t)HID*3*UPD ];
__device__ __align__(256) __nv_bfloat16 g_WfP  [ (size_t)FOUT*3*UPD ];
__device__ __align__(256) __nv_bfloat16 g_WdP  [ (size_t)INP*3*HID ];
// fp32 intermediates
__device__ __align__(256) float g_xt   [ (size_t)ROWS*UPD ];
__device__ __align__(256) float g_rt   [ (size_t)ROWS*HID ];
__device__ __align__(256) float g_xskip[ (size_t)ROWS*HID ];
__device__ __align__(256) float g_fused[ (size_t)ROWS*FOUT ];
__device__ __align__(256) float g_ht   [ (size_t)ROWS*HID ];
__device__ __align__(256) float g_dp   [ (size_t)ROWS*HID ];
__device__ __align__(256) float g_y1   [ (size_t)ROWS*HID ];

// -------------------- packed f32x2 helpers (scan) --------------------
__device__ __forceinline__ ull ffma2(ull a, ull b, ull c) {
    ull d; asm("fma.rn.f32x2 %0, %1, %2, %3;" : "=l"(d) : "l"(a), "l"(b), "l"(c)); return d;
}
__device__ __forceinline__ ull fmul2(ull a, ull b) {
    ull d; asm("mul.rn.f32x2 %0, %1, %2;" : "=l"(d) : "l"(a), "l"(b)); return d;
}
__device__ __forceinline__ ull fadd2(ull a, ull b) {
    ull d; asm("add.rn.f32x2 %0, %1, %2;" : "=l"(d) : "l"(a), "l"(b)); return d;
}
__device__ __forceinline__ ull bcast2(float x) {
    ull d; asm("mov.b64 %0, {%1, %1};" : "=l"(d) : "f"(x)); return d;
}
__device__ __forceinline__ float2 unpack2(ull v) {
    float2 f; asm("mov.b64 {%0, %1}, %2;" : "=f"(f.x), "=f"(f.y) : "l"(v)); return f;
}

// -------------------- mma / ldmatrix / cp.async helpers (plain sm_80+ PTX) --------------------
static __device__ __forceinline__ uint32_t smem_u32(const void* p) {
    uint32_t a;
    asm("{ .reg .u64 t; cvta.to.shared.u64 t, %1; cvt.u32.u64 %0, t; }" : "=r"(a) : "l"(p));
    return a;
}

#define LDSM4(r, addr) \
    asm volatile("ldmatrix.sync.aligned.m8n8.x4.shared.b16 {%0,%1,%2,%3}, [%4];" \
        : "=r"((r)[0]), "=r"((r)[1]), "=r"((r)[2]), "=r"((r)[3]) : "r"(addr))

#define MMA16816(c, a, b0, b1) \
    asm volatile("mma.sync.aligned.m16n8k16.row.col.f32.bf16.bf16.f32 " \
        "{%0,%1,%2,%3}, {%4,%5,%6,%7}, {%8,%9}, {%0,%1,%2,%3};" \
        : "+f"((c)[0]), "+f"((c)[1]), "+f"((c)[2]), "+f"((c)[3]) \
        : "r"((a)[0]), "r"((a)[1]), "r"((a)[2]), "r"((a)[3]), "r"(b0), "r"(b1))

static __device__ __forceinline__ void cp_async16(uint32_t d, const void* g, int sz) {
    asm volatile("cp.async.cg.shared.global [%0], [%1], 16, %2;"
                 :: "r"(d), "l"(g), "r"(sz) : "memory");
}
#define CP_COMMIT() asm volatile("cp.async.commit_group;" ::: "memory")
#define CP_WAIT1()  asm volatile("cp.async.wait_group 1;" ::: "memory")
#define CP_WAIT0()  asm volatile("cp.async.wait_group 0;" ::: "memory")

// smem tile: 128 rows x 4 chunks of 16B (64B/row); chunk XOR-swizzled by (row>>1)&3
static __device__ __forceinline__ uint32_t swaddr(uint32_t base, int row, int ch) {
    return base + ((uint32_t)row << 6) + ((uint32_t)((ch ^ ((row >> 1) & 3)) & 3) << 4);
}

// -------------------- generic reduction helper --------------------
__device__ __forceinline__ void block_reduce_sum2(float& s, float& s2,
                                                  float* sh, float* sh2) {
    int lane = threadIdx.x & 31, wid = threadIdx.x >> 5;
#pragma unroll
    for (int o = 16; o > 0; o >>= 1) {
        s  += __shfl_xor_sync(0xffffffffu, s,  o);
        s2 += __shfl_xor_sync(0xffffffffu, s2, o);
    }
    if (lane == 0) { sh[wid] = s; sh2[wid] = s2; }
    __syncthreads();
    float t = 0.f, t2 = 0.f;
#pragma unroll
    for (int i = 0; i < 8; i++) { t += sh[i]; t2 += sh2[i]; }
    s = t; s2 = t2;
}

__device__ __forceinline__ void split_bf16(float x, __nv_bfloat16& hi, __nv_bfloat16& lo) {
    hi = __float2bfloat16(x);
    lo = __float2bfloat16(x - __bfloat162float(hi));
}

// -------------------- LayerNorm over 768 + A-pack write --------------------
__global__ __launch_bounds__(256) void ln1_pack_kernel(const float* __restrict__ x,
                                                       const float* __restrict__ g,
                                                       const float* __restrict__ b,
                                                       __nv_bfloat16* __restrict__ p) {
    __shared__ float sh[8], sh2[8];
    int row = blockIdx.x, t = threadIdx.x;
    const float* xr = x + (size_t)row * INP;
    float v0 = xr[t], v1 = xr[t + 256], v2 = xr[t + 512];
    float s = v0 + v1 + v2;
    float s2 = v0 * v0 + v1 * v1 + v2 * v2;
    block_reduce_sum2(s, s2, sh, sh2);
    float mean = s * (1.0f / INP);
    float var  = s2 * (1.0f / INP) - mean * mean;
    float r = rsqrtf(var + 1e-6f);
    __nv_bfloat16* pr = p + (size_t)row * 3 * INP;
#pragma unroll
    for (int k = 0; k < 3; k++) {
        int j = t + k * 256;
        float v = (k == 0) ? v0 : (k == 1) ? v1 : v2;
        float y = (v - mean) * r * g[j] + b[j];
        __nv_bfloat16 hi, lo; split_bf16(y, hi, lo);
        pr[j] = hi; pr[INP + j] = lo; pr[2 * INP + j] = hi;
    }
}

// -------------------- weight B-pack: [hi | hi | lo] --------------------
__global__ void pack_b_kernel(const float* __restrict__ src,
                              __nv_bfloat16* __restrict__ dst,
                              int K, int total) {
    int i = blockIdx.x * blockDim.x + threadIdx.x;
    if (i >= total) return;
    int row = i / K, j = i % K;
    float x = src[i];
    __nv_bfloat16 hi, lo; split_bf16(x, hi, lo);
    __nv_bfloat16* d = dst + (size_t)row * 3 * K;
    d[j] = hi; d[K + j] = hi; d[2 * K + j] = lo;
}

// -------------------- warp-MMA bf16 NT GEMM: C[M,N] = A[M,K3]*B[N,K3]^T (+bias) ------------
// 256 thr = 8 warps (2x4); block tile 128x128; K-tile 32; warp tile 64x32.
__global__ __launch_bounds__(256) void gemm_mma_kernel(
    int Nn, int K3,
    const __nv_bfloat16* __restrict__ A, const __nv_bfloat16* __restrict__ B,
    const float* __restrict__ bias, float* __restrict__ Cout) {
    __shared__ __align__(1024) char sm[32768];   // A: s*8192, B: 16384 + s*8192
    uint32_t sb = smem_u32(sm);
    int tid = threadIdx.x;
    int bm = blockIdx.y * 128, bn = blockIdx.x * 128;
    int wid = tid >> 5, lane = tid & 31;
    int wm = wid >> 2, wn = wid & 3;
    int lr = lane & 7, grp = lane >> 3;
    int niter = K3 / 32;

    float acc[4][4][4];
#pragma unroll
    for (int i = 0; i < 4; i++)
#pragma unroll
        for (int j = 0; j < 4; j++)
#pragma unroll
            for (int q = 0; q < 4; q++) acc[i][j][q] = 0.f;

    auto issue_tile = [&](int it, int s) {
        int kt = it * 32;
#pragma unroll
        for (int q = 0; q < 2; q++) {
            int idx = tid + q * 256;
            int r = idx >> 2, ch = idx & 3;
            cp_async16(swaddr(sb + (uint32_t)s * 8192u, r, ch),
                       A + (size_t)(bm + r) * K3 + kt + ch * 8, 16);
            int br = bn + r;
            cp_async16(swaddr(sb + 16384u + (uint32_t)s * 8192u, r, ch),
                       B + (size_t)(br < Nn ? br : 0) * K3 + kt + ch * 8,
                       br < Nn ? 16 : 0);
        }
        CP_COMMIT();
    };

    issue_tile(0, 0);
    for (int it = 0; it < niter; it++) {
        int s = it & 1;
        if (it + 1 < niter) { issue_tile(it + 1, s ^ 1); CP_WAIT1(); }
        else                { CP_WAIT0(); }
        __syncthreads();

        uint32_t Abase = sb + (uint32_t)s * 8192u;
        uint32_t Bbase = sb + 16384u + (uint32_t)s * 8192u;
#pragma unroll
        for (int ks = 0; ks < 2; ks++) {
            int klo = ks * 2;
            uint32_t a[4][4];
#pragma unroll
            for (int fm = 0; fm < 4; fm++) {
                int row = wm * 64 + fm * 16 + lr + ((grp & 1) << 3);
                int ch = klo + (grp >> 1);
                LDSM4(a[fm], swaddr(Abase, row, ch));
            }
            uint32_t b[2][4];
#pragma unroll
            for (int np = 0; np < 2; np++) {
                int row = wn * 32 + np * 16 + lr + ((grp >> 1) << 3);
                int ch = klo + (grp & 1);
                LDSM4(b[np], swaddr(Bbase, row, ch));
            }
#pragma unroll
            for (int fm = 0; fm < 4; fm++)
#pragma unroll
                for (int fn = 0; fn < 4; fn++) {
                    int np = fn >> 1, fl = fn & 1;
                    MMA16816(acc[fm][fn], a[fm], b[np][fl * 2], b[np][fl * 2 + 1]);
                }
        }
        __syncthreads();
    }

    // epilogue: c0,c1 -> (row, col..+1); c2,c3 -> (row+8, col..+1)
    int qr = lane >> 2, qc = lane & 3;
#pragma unroll
    for (int fn = 0; fn < 4; fn++) {
        int np = fn >> 1, fl = fn & 1;
        int col = bn + wn * 32 + np * 16 + fl * 8 + qc * 2;
        if (col < Nn) {
            float bx = bias ? bias[col] : 0.f;
            float by = bias ? bias[col + 1] : 0.f;
#pragma unroll
            for (int fm = 0; fm < 4; fm++) {
                int row0 = bm + wm * 64 + fm * 16 + qr;
                float2 v0 = make_float2(acc[fm][fn][0] + bx, acc[fm][fn][1] + by);
                float2 v1 = make_float2(acc[fm][fn][2] + bx, acc[fm][fn][3] + by);
                *(float2*)(Cout + (size_t)row0 * Nn + col) = v0;
                *(float2*)(Cout + (size_t)(row0 + 8) * Nn + col) = v1;
            }
        }
    }
}

// -------------------- causal 4-tap feature conv + silu + A-pack write --------------------
__global__ void conv_silu_pack_kernel(const float* __restrict__ xt,
                                      const float* __restrict__ w,
                                      __nv_bfloat16* __restrict__ p) {
    int i = blockIdx.x * blockDim.x + threadIdx.x;
    if (i >= ROWS * UPD) return;
    int row = i / UPD, j = i % UPD;
    float acc = w[3] * xt[i];
    if (j >= 1) acc += w[2] * xt[i - 1];
    if (j >= 2) acc += w[1] * xt[i - 2];
    if (j >= 3) acc += w[0] * xt[i - 3];
    float xc = acc / (1.0f + expf(-acc));   // silu
    __nv_bfloat16 hi, lo; split_bf16(xc, hi, lo);
    __nv_bfloat16* pr = p + (size_t)row * 3 * UPD;
    pr[j] = hi; pr[UPD + j] = lo; pr[2 * UPD + j] = hi;
}

// -------------------- sequential mLSTM scan: one block per (b,h) --------------------
__global__ __launch_bounds__(96) void scan_kernel(const float* __restrict__ fused,
                                                  float* __restrict__ ht,
                                                  float* __restrict__ dpo,
                                                  float* __restrict__ outC,
                                                  float* __restrict__ outN,
                                                  float* __restrict__ outM) {
    int bh = blockIdx.x, b = bh >> 3, h = bh & 7;
    int d = threadIdx.x;          // 0..95
    const float inv = rsqrtf((float)HD);

    ull C[48];
#pragma unroll
    for (int e = 0; e < 48; e++) C[e] = 0ull;
    float nd = 1.0f, m = 0.0f;

    __shared__ __align__(16) float qs[2][HD];
    __shared__ __align__(16) float ks[2][HD];

    size_t rb = (size_t)b * SEQ * FOUT;
    float qv = fused[rb + 784  + h * HD + d];
    float kv = fused[rb + 1552 + h * HD + d];
    float vv = fused[rb + 2320 + h * HD + d];
    float iv = fused[rb + h];
    float fv = fused[rb + 8 + h];

    for (int s = 0; s < SEQ; s++) {
        int p = s & 1;
        float qd = qv, kd = kv * inv, vd = vv;
        float i_t = CAPV * tanhf(iv * (1.0f / CAPV));
        float f_t = CAPV * tanhf(fv * (1.0f / CAPV));
        qs[p][d] = qd; ks[p][d] = kd;
        __syncthreads();

        if (s + 1 < SEQ) {
            size_t rb2 = ((size_t)b * SEQ + s + 1) * FOUT;
            qv = fused[rb2 + 784  + h * HD + d];
            kv = fused[rb2 + 1552 + h * HD + d];
            vv = fused[rb2 + 2320 + h * HD + d];
            iv = fused[rb2 + h];
            fv = fused[rb2 + 8 + h];
        }

        float m_t = fmaxf(f_t + m, i_t);
        float ie = expf(i_t - m_t);
        float fe = expf(f_t - m_t + m);
        m = m_t;

        ull pa  = bcast2(ie * vd);
        ull pfe = bcast2(fe);
        const ulonglong2* kp2 = (const ulonglong2*)ks[p];
        const ulonglong2* qp2 = (const ulonglong2*)qs[p];
        ull hn0 = 0ull, hn1 = 0ull, hn2a = 0ull, hn3 = 0ull;
#pragma unroll
        for (int e2 = 0; e2 < 24; e2 += 2) {
            ulonglong2 kk0 = kp2[e2],     qq0 = qp2[e2];
            ulonglong2 kk1 = kp2[e2 + 1], qq1 = qp2[e2 + 1];
            ull c;
            c = ffma2(pa, kk0.x, fmul2(pfe, C[2 * e2 + 0])); C[2 * e2 + 0] = c; hn0  = ffma2(c, qq0.x, hn0);
            c = ffma2(pa, kk0.y, fmul2(pfe, C[2 * e2 + 1])); C[2 * e2 + 1] = c; hn1  = ffma2(c, qq0.y, hn1);
            c = ffma2(pa, kk1.x, fmul2(pfe, C[2 * e2 + 2])); C[2 * e2 + 2] = c; hn2a = ffma2(c, qq1.x, hn2a);
            c = ffma2(pa, kk1.y, fmul2(pfe, C[2 * e2 + 3])); C[2 * e2 + 3] = c; hn3  = ffma2(c, qq1.y, hn3);
        }
        float2 hf = unpack2(fadd2(fadd2(hn0, hn1), fadd2(hn2a, hn3)));
        float hnv = hf.x + hf.y;

        nd = fmaf(ie, kd, fe * nd);
        size_t o = ((size_t)b * SEQ + s) * HID + h * HD + d;
        ht[o]  = hnv;
        dpo[o] = nd * qd;
    }

    float* Cr = outC + ((size_t)bh * HD + d) * HD;
#pragma unroll
    for (int e = 0; e < 48; e++) {
        float2 f = unpack2(C[e]);
        *(float2*)(Cr + 2 * e) = f;
    }
    outN[bh * HD + d] = nd;
    if (d == 0) outM[bh] = m;
}

// -------------------- denom reduce + o-gate, LN2, A-pack write --------------------
__global__ __launch_bounds__(256) void post_pack_kernel(const float* __restrict__ fused,
                                                        const float* __restrict__ ht,
                                                        const float* __restrict__ dp,
                                                        const float* __restrict__ g,
                                                        const float* __restrict__ b,
                                                        __nv_bfloat16* __restrict__ p) {
    __shared__ float sh[8], sh2[8], sden[8];
    int row = blockIdx.x, t = threadIdx.x;
    int w = t >> 5, lane = t & 31;

    const float* dpr = dp + (size_t)row * HID;
    float sdp = dpr[w * 96 + lane] + dpr[w * 96 + 32 + lane] + dpr[w * 96 + 64 + lane];
#pragma unroll
    for (int o = 16; o > 0; o >>= 1) sdp += __shfl_xor_sync(0xffffffffu, sdp, o);
    if (lane == 0) sden[w] = fmaxf(sdp, 1.0f);
    __syncthreads();

    const float* fr = fused + (size_t)row * FOUT + 16;
    const float* hr = ht + (size_t)row * HID;
    float hv[3]; float s = 0.f, s2 = 0.f;
#pragma unroll
    for (int k = 0; k < 3; k++) {
        int j = t + k * 256;
        float oraw = fr[j];
        float og = 1.0f / (1.0f + expf(-CAPV * tanhf(oraw * (1.0f / CAPV))));
        float h = og * (hr[j] / sden[j / 96]);
        hv[k] = h; s += h; s2 += h * h;
    }
    block_reduce_sum2(s, s2, sh, sh2);
    float mean = s * (1.0f / HID);
    float var  = s2 * (1.0f / HID) - mean * mean;
    float r = rsqrtf(var + 1e-6f);
    __nv_bfloat16* pr = p + (size_t)row * 3 * HID;
#pragma unroll
    for (int k = 0; k < 3; k++) {
        int j = t + k * 256;
        float y = (hv[k] - mean) * r * g[j] + b[j];
        __nv_bfloat16 hi, lo; split_bf16(y, hi, lo);
        pr[j] = hi; pr[HID + j] = lo; pr[2 * HID + j] = hi;
    }
}

// -------------------- final fuse: (y1 + xskip)*silu(rt) + x --------------------
__global__ void final_kernel(const float* __restrict__ y1,
                             const float* __restrict__ xskip,
                             const float* __restrict__ rt,
                             const float* __restrict__ x,
                             float* __restrict__ out) {
    int i = blockIdx.x * blockDim.x + threadIdx.x;
    if (i >= ROWS * HID) return;
    float r = rt[i];
    float sil = r / (1.0f + expf(-r));
    out[i] = (y1[i] + xskip[i]) * sil + x[i];
}

// -------------------- launch --------------------
extern "C" void kernel_launch(void* const* d_in, const int* in_sizes, int n_in,
                              void* d_out, int out_size) {
    (void)in_sizes; (void)n_in; (void)out_size;
    const float* x       = (const float*)d_in[0];
    const float* ln1_g   = (const float*)d_in[1];
    const float* ln1_b   = (const float*)d_in[2];
    const float* W_up_l  = (const float*)d_in[3];
    const float* W_up_r  = (const float*)d_in[4];
    const float* conv_w  = (const float*)d_in[5];
    const float* W_skip  = (const float*)d_in[6];
    const float* fused_W = (const float*)d_in[7];
    const float* fused_b = (const float*)d_in[8];
    const float* ln2_g   = (const float*)d_in[9];
    const float* ln2_b   = (const float*)d_in[10];
    const float* W_down  = (const float*)d_in[11];
    float* out = (float*)d_out;

    __nv_bfloat16 *xnP, *xcP, *hn2P, *WuplP, *WuprP, *WskipP, *WfP, *WdP;
    float *xt, *rt, *xskip, *fused, *ht, *dp, *y1;
    cudaGetSymbolAddress((void**)&xnP,   g_xnP);
    cudaGetSymbolAddress((void**)&xcP,   g_xcP);
    cudaGetSymbolAddress((void**)&hn2P,  g_hn2P);
    cudaGetSymbolAddress((void**)&WuplP, g_WuplP);
    cudaGetSymbolAddress((void**)&WuprP, g_WuprP);
    cudaGetSymbolAddress((void**)&WskipP,g_WskipP);
    cudaGetSymbolAddress((void**)&WfP,   g_WfP);
    cudaGetSymbolAddress((void**)&WdP,   g_WdP);
    cudaGetSymbolAddress((void**)&xt,    g_xt);
    cudaGetSymbolAddress((void**)&rt,    g_rt);
    cudaGetSymbolAddress((void**)&xskip, g_xskip);
    cudaGetSymbolAddress((void**)&fused, g_fused);
    cudaGetSymbolAddress((void**)&ht,    g_ht);
    cudaGetSymbolAddress((void**)&dp,    g_dp);
    cudaGetSymbolAddress((void**)&y1,    g_y1);

    // weight packs (B side: hi|hi|lo)
    pack_b_kernel<<<(UPD * INP + 255) / 256, 256>>>(W_up_l,  WuplP, INP, UPD * INP);
    pack_b_kernel<<<(HID * INP + 255) / 256, 256>>>(W_up_r,  WuprP, INP, HID * INP);
    pack_b_kernel<<<(HID * UPD + 255) / 256, 256>>>(W_skip,  WskipP, UPD, HID * UPD);
    pack_b_kernel<<<(FOUT * UPD + 255) / 256, 256>>>(fused_W, WfP, UPD, FOUT * UPD);
    pack_b_kernel<<<(INP * HID + 255) / 256, 256>>>(W_down,  WdP, HID, INP * HID);

    // LN1 + A-pack
    ln1_pack_kernel<<<ROWS, 256>>>(x, ln1_g, ln1_b, xnP);

    // up projections (K3 = 2304)
    gemm_mma_kernel<<<dim3(UPD / 128, ROWS / 128), 256>>>(UPD, 3 * INP, xnP, WuplP, nullptr, xt);
    gemm_mma_kernel<<<dim3(HID / 128, ROWS / 128), 256>>>(HID, 3 * INP, xnP, WuprP, nullptr, rt);

    // conv + silu + A-pack
    conv_silu_pack_kernel<<<(ROWS * UPD + 255) / 256, 256>>>(xt, conv_w, xcP);

    // skip + fused (K3 = 4608)
    gemm_mma_kernel<<<dim3(HID / 128, ROWS / 128), 256>>>(HID, 3 * UPD, xcP, WskipP, nullptr, xskip);
    gemm_mma_kernel<<<dim3((FOUT + 127) / 128, ROWS / 128), 256>>>(FOUT, 3 * UPD, xcP, WfP, fused_b, fused);

    // sequential scan
    float* outC = out + (size_t)ROWS * INP;
    float* outN = outC + (size_t)BATCH * NH * HD * HD;
    float* outM = outN + (size_t)BATCH * NH * HD;
    scan_kernel<<<BATCH * NH, 96>>>(fused, ht, dp, outC, outN, outM);

    // post: o-gate + LN2 + A-pack
    post_pack_kernel<<<ROWS, 256>>>(fused, ht, dp, ln2_g, ln2_b, hn2P);

    // down projection (K3 = 2304)
    gemm_mma_kernel<<<dim3(HID / 128, ROWS / 128), 256>>>(HID, 3 * HID, hn2P, WdP, nullptr, y1);

    final_kernel<<<(ROWS * HID + 255) / 256, 256>>>(y1, xskip, rt, x, out);
}

// round 13
// speedup vs baseline: 2.2946x; 1.1041x over previous
#include <cuda_runtime.h>
#include <cuda_bf16.h>
#include <cstdint>

#define INP   768
#define HID   768
#define NH    8
#define HD    96
#define UPD   1536
#define FOUT  3088
#define BATCH 8
#define SEQ   1024
#define ROWS  (BATCH*SEQ)   /* 8192 */
#define CAPV  15.0f

#define NUP   (UPD + HID)          /* 2304 merged up-proj width  */
#define NSF   (HID + FOUT)         /* 3856 merged skip+fused width */
#define OFF_I (HID + 0)            /* 768  */
#define OFF_F (HID + 8)            /* 776  */
#define OFF_O (HID + 16)           /* 784  */
#define OFF_Q (HID + 784)          /* 1552 */
#define OFF_K (HID + 1552)         /* 2320 */
#define OFF_V (HID + 2320)         /* 3088 */

typedef unsigned long long ull;

// -------------------- scratch (no allocs allowed) --------------------
__device__ __align__(256) __nv_bfloat16 g_xnP  [ (size_t)ROWS*3*INP ];
__device__ __align__(256) __nv_bfloat16 g_xcP  [ (size_t)ROWS*3*UPD ];
__device__ __align__(256) __nv_bfloat16 g_hn2P [ (size_t)ROWS*3*HID ];
__device__ __align__(256) __nv_bfloat16 g_WupP [ (size_t)NUP*3*INP ];
__device__ __align__(256) __nv_bfloat16 g_WsfP [ (size_t)NSF*3*UPD ];
__device__ __align__(256) __nv_bfloat16 g_WdP  [ (size_t)INP*3*HID ];
__device__ __align__(256) float g_upM  [ (size_t)ROWS*NUP ];   // [xt | rt]
__device__ __align__(256) float g_sfM  [ (size_t)ROWS*NSF ];   // [xskip | fused]
__device__ __align__(256) float g_ht0  [ (size_t)ROWS*HID ];
__device__ __align__(256) float g_ht1  [ (size_t)ROWS*HID ];
__device__ __align__(256) float g_dp   [ (size_t)ROWS*HID ];
__device__ __align__(256) float g_y1   [ (size_t)ROWS*HID ];
__device__ __align__(256) float g_biasM[ NSF ];

// -------------------- packed f32x2 helpers --------------------
__device__ __forceinline__ ull ffma2(ull a, ull b, ull c) {
    ull d; asm("fma.rn.f32x2 %0, %1, %2, %3;" : "=l"(d) : "l"(a), "l"(b), "l"(c)); return d;
}
__device__ __forceinline__ ull fmul2(ull a, ull b) {
    ull d; asm("mul.rn.f32x2 %0, %1, %2;" : "=l"(d) : "l"(a), "l"(b)); return d;
}
__device__ __forceinline__ ull fadd2(ull a, ull b) {
    ull d; asm("add.rn.f32x2 %0, %1, %2;" : "=l"(d) : "l"(a), "l"(b)); return d;
}
__device__ __forceinline__ ull bcast2(float x) {
    ull d; asm("mov.b64 %0, {%1, %1};" : "=l"(d) : "f"(x)); return d;
}
__device__ __forceinline__ float2 unpack2(ull v) {
    float2 f; asm("mov.b64 {%0, %1}, %2;" : "=f"(f.x), "=f"(f.y) : "l"(v)); return f;
}

// -------------------- mma / ldmatrix / cp.async helpers --------------------
static __device__ __forceinline__ uint32_t smem_u32(const void* p) {
    uint32_t a;
    asm("{ .reg .u64 t; cvta.to.shared.u64 t, %1; cvt.u32.u64 %0, t; }" : "=r"(a) : "l"(p));
    return a;
}
#define LDSM4(r, addr) \
    asm volatile("ldmatrix.sync.aligned.m8n8.x4.shared.b16 {%0,%1,%2,%3}, [%4];" \
        : "=r"((r)[0]), "=r"((r)[1]), "=r"((r)[2]), "=r"((r)[3]) : "r"(addr))
#define MMA16816(c, a, b0, b1) \
    asm volatile("mma.sync.aligned.m16n8k16.row.col.f32.bf16.bf16.f32 " \
        "{%0,%1,%2,%3}, {%4,%5,%6,%7}, {%8,%9}, {%0,%1,%2,%3};" \
        : "+f"((c)[0]), "+f"((c)[1]), "+f"((c)[2]), "+f"((c)[3]) \
        : "r"((a)[0]), "r"((a)[1]), "r"((a)[2]), "r"((a)[3]), "r"(b0), "r"(b1))
static __device__ __forceinline__ void cp_async16(uint32_t d, const void* g, int sz) {
    asm volatile("cp.async.cg.shared.global [%0], [%1], 16, %2;"
                 :: "r"(d), "l"(g), "r"(sz) : "memory");
}
#define CP_COMMIT() asm volatile("cp.async.commit_group;" ::: "memory")
#define CP_WAIT1()  asm volatile("cp.async.wait_group 1;" ::: "memory")
#define CP_WAIT0()  asm volatile("cp.async.wait_group 0;" ::: "memory")

// 128B rows, 8 chunks of 16B, XOR-swizzled by row&7
static __device__ __forceinline__ uint32_t sw128(uint32_t base, int row, int ch) {
    return base + ((uint32_t)row << 7) + ((uint32_t)((ch ^ (row & 7)) & 7) << 4);
}

// -------------------- reduction helper --------------------
__device__ __forceinline__ void block_reduce_sum2(float& s, float& s2,
                                                  float* sh, float* sh2) {
    int lane = threadIdx.x & 31, wid = threadIdx.x >> 5;
#pragma unroll
    for (int o = 16; o > 0; o >>= 1) {
        s  += __shfl_xor_sync(0xffffffffu, s,  o);
        s2 += __shfl_xor_sync(0xffffffffu, s2, o);
    }
    if (lane == 0) { sh[wid] = s; sh2[wid] = s2; }
    __syncthreads();
    float t = 0.f, t2 = 0.f;
#pragma unroll
    for (int i = 0; i < 8; i++) { t += sh[i]; t2 += sh2[i]; }
    s = t; s2 = t2;
}

__device__ __forceinline__ void split_bf16(float x, __nv_bfloat16& hi, __nv_bfloat16& lo) {
    hi = __float2bfloat16(x);
    lo = __float2bfloat16(x - __bfloat162float(hi));
}

// -------------------- LayerNorm over 768 + A-pack write --------------------
__global__ __launch_bounds__(256) void ln1_pack_kernel(const float* __restrict__ x,
                                                       const float* __restrict__ g,
                                                       const float* __restrict__ b,
                                                       __nv_bfloat16* __restrict__ p) {
    __shared__ float sh[8], sh2[8];
    int row = blockIdx.x, t = threadIdx.x;
    const float* xr = x + (size_t)row * INP;
    float v0 = xr[t], v1 = xr[t + 256], v2 = xr[t + 512];
    float s = v0 + v1 + v2;
    float s2 = v0 * v0 + v1 * v1 + v2 * v2;
    block_reduce_sum2(s, s2, sh, sh2);
    float mean = s * (1.0f / INP);
    float var  = s2 * (1.0f / INP) - mean * mean;
    float r = rsqrtf(var + 1e-6f);
    __nv_bfloat16* pr = p + (size_t)row * 3 * INP;
#pragma unroll
    for (int k = 0; k < 3; k++) {
        int j = t + k * 256;
        float v = (k == 0) ? v0 : (k == 1) ? v1 : v2;
        float y = (v - mean) * r * g[j] + b[j];
        __nv_bfloat16 hi, lo; split_bf16(y, hi, lo);
        pr[j] = hi; pr[INP + j] = lo; pr[2 * INP + j] = hi;
    }
}

// -------------------- weight B-pack: [hi | hi | lo] --------------------
__global__ void pack_b_kernel(const float* __restrict__ src,
                              __nv_bfloat16* __restrict__ dst,
                              int K, int total) {
    int i = blockIdx.x * blockDim.x + threadIdx.x;
    if (i >= total) return;
    int row = i / K, j = i % K;
    float x = src[i];
    __nv_bfloat16 hi, lo; split_bf16(x, hi, lo);
    __nv_bfloat16* d = dst + (size_t)row * 3 * K;
    d[j] = hi; d[K + j] = hi; d[2 * K + j] = lo;
}

__global__ void bias_build_kernel(const float* __restrict__ fb, float* __restrict__ bm) {
    int i = blockIdx.x * blockDim.x + threadIdx.x;
    if (i >= NSF) return;
    bm[i] = (i < HID) ? 0.f : fb[i - HID];
}

// -------------------- warp-MMA bf16 NT GEMM, K64 tiles, 3-stage cp.async ------------
// 256 thr = 8 warps (2x4); block tile 128x128; warp tile 64x32; dyn smem 96KB.
__global__ __launch_bounds__(256) void gemm_mma_kernel(
    int Nn, int K3,
    const __nv_bfloat16* __restrict__ A, const __nv_bfloat16* __restrict__ B,
    const float* __restrict__ bias, float* __restrict__ Cout) {
    extern __shared__ __align__(1024) char sm[];
    uint32_t sA = smem_u32(sm);            // 3 x 16KB
    uint32_t sB = sA + 49152u;             // 3 x 16KB
    int tid = threadIdx.x;
    int bm = blockIdx.y * 128, bn = blockIdx.x * 128;
    int wid = tid >> 5, lane = tid & 31;
    int wm = wid >> 2, wn = wid & 3;
    int lr = lane & 7, grp = lane >> 3;
    int niter = K3 >> 6;

    float acc[4][4][4];
#pragma unroll
    for (int i = 0; i < 4; i++)
#pragma unroll
        for (int j = 0; j < 4; j++)
#pragma unroll
            for (int q = 0; q < 4; q++) acc[i][j][q] = 0.f;

    auto issue_stage = [&](int it, int s) {
        int kt = it << 6;
#pragma unroll
        for (int q = 0; q < 4; q++) {
            int idx = tid + q * 256;          // 1024 = 128 rows x 8 ch
            int r = idx >> 3, ch = idx & 7;
            cp_async16(sw128(sA + (uint32_t)s * 16384u, r, ch),
                       A + (size_t)(bm + r) * K3 + kt + ch * 8, 16);
            int br = bn + r;
            cp_async16(sw128(sB + (uint32_t)s * 16384u, r, ch),
                       B + (size_t)(br < Nn ? br : 0) * K3 + kt + ch * 8,
                       br < Nn ? 16 : 0);
        }
        CP_COMMIT();
    };

    issue_stage(0, 0);
    if (niter > 1) issue_stage(1, 1);

    for (int it = 0; it < niter; it++) {
        int s = it % 3;
        if (it + 1 < niter) CP_WAIT1(); else CP_WAIT0();
        __syncthreads();

        uint32_t Ab = sA + (uint32_t)s * 16384u;
        uint32_t Bb = sB + (uint32_t)s * 16384u;
#pragma unroll
        for (int ks = 0; ks < 4; ks++) {
            uint32_t a[4][4];
#pragma unroll
            for (int fm = 0; fm < 4; fm++) {
                int row = wm * 64 + fm * 16 + lr + ((grp & 1) << 3);
                int ch = ks * 2 + (grp >> 1);
                LDSM4(a[fm], sw128(Ab, row, ch));
            }
            uint32_t b[2][4];
#pragma unroll
            for (int np = 0; np < 2; np++) {
                int row = wn * 32 + np * 16 + lr + ((grp >> 1) << 3);
                int ch = ks * 2 + (grp & 1);
                LDSM4(b[np], sw128(Bb, row, ch));
            }
#pragma unroll
            for (int fm = 0; fm < 4; fm++)
#pragma unroll
                for (int fn = 0; fn < 4; fn++) {
                    int np = fn >> 1, fl = fn & 1;
                    MMA16816(acc[fm][fn], a[fm], b[np][fl * 2], b[np][fl * 2 + 1]);
                }
        }
        if (it + 2 < niter) issue_stage(it + 2, (it + 2) % 3);
    }

    int qr = lane >> 2, qc = lane & 3;
#pragma unroll
    for (int fn = 0; fn < 4; fn++) {
        int np = fn >> 1, fl = fn & 1;
        int col = bn + wn * 32 + np * 16 + fl * 8 + qc * 2;
        if (col < Nn) {
            float bx = bias ? bias[col] : 0.f;
            float by = bias ? bias[col + 1] : 0.f;
#pragma unroll
            for (int fm = 0; fm < 4; fm++) {
                int row0 = bm + wm * 64 + fm * 16 + qr;
                float2 v0 = make_float2(acc[fm][fn][0] + bx, acc[fm][fn][1] + by);
                float2 v1 = make_float2(acc[fm][fn][2] + bx, acc[fm][fn][3] + by);
                *(float2*)(Cout + (size_t)row0 * Nn + col) = v0;
                *(float2*)(Cout + (size_t)(row0 + 8) * Nn + col) = v1;
            }
        }
    }
}

// -------------------- causal conv + silu + A-pack (xt from merged upM) --------------------
__global__ void conv_silu_pack_kernel(const float* __restrict__ up,
                                      const float* __restrict__ w,
                                      __nv_bfloat16* __restrict__ p) {
    int i = blockIdx.x * blockDim.x + threadIdx.x;
    if (i >= ROWS * UPD) return;
    int row = i / UPD, j = i % UPD;
    const float* xr = up + (size_t)row * NUP;
    float acc = w[3] * xr[j];
    if (j >= 1) acc += w[2] * xr[j - 1];
    if (j >= 2) acc += w[1] * xr[j - 2];
    if (j >= 3) acc += w[0] * xr[j - 3];
    float xc = acc / (1.0f + expf(-acc));   // silu
    __nv_bfloat16 hi, lo; split_bf16(xc, hi, lo);
    __nv_bfloat16* pr = p + (size_t)row * 3 * UPD;
    pr[j] = hi; pr[UPD + j] = lo; pr[2 * UPD + j] = hi;
}

// -------------------- sequential mLSTM scan: 2 blocks per (b,h), e-split --------------------
__global__ __launch_bounds__(96) void scan_kernel(const float* __restrict__ sf,
                                                  float* __restrict__ ht0,
                                                  float* __restrict__ ht1,
                                                  float* __restrict__ dpo,
                                                  float* __restrict__ outC,
                                                  float* __restrict__ outN,
                                                  float* __restrict__ outM) {
    int bx = blockIdx.x;
    int bh = bx >> 1, sp = bx & 1;
    int b = bh >> 3, h = bh & 7;
    int e0 = sp * 48;
    int t = threadIdx.x;          // d = row of C
    const float inv = rsqrtf((float)HD);

    ull C[24];                    // e-range [e0, e0+48) as packed pairs
#pragma unroll
    for (int e = 0; e < 24; e++) C[e] = 0ull;
    float nd = 1.0f, m = 0.0f;

    __shared__ __align__(16) float qs[2][48];
    __shared__ __align__(16) float ks[2][48];

    const float* base = sf + (size_t)b * SEQ * NSF;
    float* htp = sp ? ht1 : ht0;

    float qv = 0.f, kv = 0.f;
    if (t < 48) {
        qv = base[OFF_Q + h * HD + e0 + t];
        kv = base[OFF_K + h * HD + e0 + t];
    }
    float vv = base[OFF_V + h * HD + t];
    float iv = base[OFF_I + h];
    float fv = base[OFF_F + h];

    for (int s = 0; s < SEQ; s++) {
        int p = s & 1;
        float qd = qv, kd = kv * inv, vd = vv;
        float i_t = CAPV * tanhf(iv * (1.0f / CAPV));
        float f_t = CAPV * tanhf(fv * (1.0f / CAPV));
        if (t < 48) { qs[p][t] = qd; ks[p][t] = kd; }
        __syncthreads();

        if (s + 1 < SEQ) {
            const float* b2 = base + (size_t)(s + 1) * NSF;
            if (t < 48) {
                qv = b2[OFF_Q + h * HD + e0 + t];
                kv = b2[OFF_K + h * HD + e0 + t];
            }
            vv = b2[OFF_V + h * HD + t];
            iv = b2[OFF_I + h];
            fv = b2[OFF_F + h];
        }

        float m_t = fmaxf(f_t + m, i_t);
        float ie = expf(i_t - m_t);
        float fe = expf(f_t - m_t + m);
        m = m_t;

        ull pa  = bcast2(ie * vd);
        ull pfe = bcast2(fe);
        const ulonglong2* kp2 = (const ulonglong2*)ks[p];
        const ulonglong2* qp2 = (const ulonglong2*)qs[p];
        ull hn0 = 0ull, hn1 = 0ull, hn2a = 0ull, hn3 = 0ull;
#pragma unroll
        for (int e2 = 0; e2 < 12; e2 += 2) {
            ulonglong2 kk0 = kp2[e2],     qq0 = qp2[e2];
            ulonglong2 kk1 = kp2[e2 + 1], qq1 = qp2[e2 + 1];
            ull c;
            c = ffma2(pa, kk0.x, fmul2(pfe, C[2 * e2 + 0])); C[2 * e2 + 0] = c; hn0  = ffma2(c, qq0.x, hn0);
            c = ffma2(pa, kk0.y, fmul2(pfe, C[2 * e2 + 1])); C[2 * e2 + 1] = c; hn1  = ffma2(c, qq0.y, hn1);
            c = ffma2(pa, kk1.x, fmul2(pfe, C[2 * e2 + 2])); C[2 * e2 + 2] = c; hn2a = ffma2(c, qq1.x, hn2a);
            c = ffma2(pa, kk1.y, fmul2(pfe, C[2 * e2 + 3])); C[2 * e2 + 3] = c; hn3  = ffma2(c, qq1.y, hn3);
        }
        float2 hf = unpack2(fadd2(fadd2(hn0, hn1), fadd2(hn2a, hn3)));
        float hnv = hf.x + hf.y;

        size_t o = ((size_t)b * SEQ + s) * HID + h * HD;
        htp[o + t] = hnv;               // partial over e-range
        if (t < 48) {
            nd = fmaf(ie, kd, fe * nd);
            dpo[o + e0 + t] = nd * qd;  // disjoint d across the two splits
        }
    }

    // final state outputs
    float* Cr = outC + ((size_t)bh * HD + t) * HD + e0;
#pragma unroll
    for (int e = 0; e < 24; e++) {
        float2 f = unpack2(C[e]);
        *(float2*)(Cr + 2 * e) = f;
    }
    if (t < 48) outN[bh * HD + e0 + t] = nd;
    if (sp == 0 && t == 0) outM[bh] = m;
}

// -------------------- denom reduce + o-gate, LN2, A-pack write --------------------
__global__ __launch_bounds__(256) void post_pack_kernel(const float* __restrict__ sf,
                                                        const float* __restrict__ ht0,
                                                        const float* __restrict__ ht1,
                                                        const float* __restrict__ dp,
                                                        const float* __restrict__ g,
                                                        const float* __restrict__ b,
                                                        __nv_bfloat16* __restrict__ p) {
    __shared__ float sh[8], sh2[8], sden[8];
    int row = blockIdx.x, t = threadIdx.x;
    int w = t >> 5, lane = t & 31;

    const float* dpr = dp + (size_t)row * HID;
    float sdp = dpr[w * 96 + lane] + dpr[w * 96 + 32 + lane] + dpr[w * 96 + 64 + lane];
#pragma unroll
    for (int o = 16; o > 0; o >>= 1) sdp += __shfl_xor_sync(0xffffffffu, sdp, o);
    if (lane == 0) sden[w] = fmaxf(sdp, 1.0f);
    __syncthreads();

    const float* fr = sf + (size_t)row * NSF + OFF_O;
    const float* h0 = ht0 + (size_t)row * HID;
    const float* h1 = ht1 + (size_t)row * HID;
    float hv[3]; float s = 0.f, s2 = 0.f;
#pragma unroll
    for (int k = 0; k < 3; k++) {
        int j = t + k * 256;
        float oraw = fr[j];
        float og = 1.0f / (1.0f + expf(-CAPV * tanhf(oraw * (1.0f / CAPV))));
        float h = og * ((h0[j] + h1[j]) / sden[j / 96]);
        hv[k] = h; s += h; s2 += h * h;
    }
    block_reduce_sum2(s, s2, sh, sh2);
    float mean = s * (1.0f / HID);
    float var  = s2 * (1.0f / HID) - mean * mean;
    float r = rsqrtf(var + 1e-6f);
    __nv_bfloat16* pr = p + (size_t)row * 3 * HID;
#pragma unroll
    for (int k = 0; k < 3; k++) {
        int j = t + k * 256;
        float y = (hv[k] - mean) * r * g[j] + b[j];
        __nv_bfloat16 hi, lo; split_bf16(y, hi, lo);
        pr[j] = hi; pr[HID + j] = lo; pr[2 * HID + j] = hi;
    }
}

// -------------------- final fuse: (y1 + xskip)*silu(rt) + x --------------------
__global__ void final_kernel(const float* __restrict__ y1,
                             const float* __restrict__ sf,
                             const float* __restrict__ up,
                             const float* __restrict__ x,
                             float* __restrict__ out) {
    int i = blockIdx.x * blockDim.x + threadIdx.x;
    if (i >= ROWS * HID) return;
    int row = i / HID, j = i % HID;
    float r = up[(size_t)row * NUP + UPD + j];      // rt
    float sk = sf[(size_t)row * NSF + j];           // xskip
    float sil = r / (1.0f + expf(-r));
    out[i] = (y1[i] + sk) * sil + x[i];
}

// -------------------- launch --------------------
#define GEMM_SMEM (3 * 32768)

extern "C" void kernel_launch(void* const* d_in, const int* in_sizes, int n_in,
                              void* d_out, int out_size) {
    (void)in_sizes; (void)n_in; (void)out_size;
    const float* x       = (const float*)d_in[0];
    const float* ln1_g   = (const float*)d_in[1];
    const float* ln1_b   = (const float*)d_in[2];
    const float* W_up_l  = (const float*)d_in[3];
    const float* W_up_r  = (const float*)d_in[4];
    const float* conv_w  = (const float*)d_in[5];
    const float* W_skip  = (const float*)d_in[6];
    const float* fused_W = (const float*)d_in[7];
    const float* fused_b = (const float*)d_in[8];
    const float* ln2_g   = (const float*)d_in[9];
    const float* ln2_b   = (const float*)d_in[10];
    const float* W_down  = (const float*)d_in[11];
    float* out = (float*)d_out;

    __nv_bfloat16 *xnP, *xcP, *hn2P, *WupP, *WsfP, *WdP;
    float *upM, *sfM, *ht0, *ht1, *dp, *y1, *biasM;
    cudaGetSymbolAddress((void**)&xnP,   g_xnP);
    cudaGetSymbolAddress((void**)&xcP,   g_xcP);
    cudaGetSymbolAddress((void**)&hn2P,  g_hn2P);
    cudaGetSymbolAddress((void**)&WupP,  g_WupP);
    cudaGetSymbolAddress((void**)&WsfP,  g_WsfP);
    cudaGetSymbolAddress((void**)&WdP,   g_WdP);
    cudaGetSymbolAddress((void**)&upM,   g_upM);
    cudaGetSymbolAddress((void**)&sfM,   g_sfM);
    cudaGetSymbolAddress((void**)&ht0,   g_ht0);
    cudaGetSymbolAddress((void**)&ht1,   g_ht1);
    cudaGetSymbolAddress((void**)&dp,    g_dp);
    cudaGetSymbolAddress((void**)&y1,    g_y1);
    cudaGetSymbolAddress((void**)&biasM, g_biasM);

    cudaFuncSetAttribute(gemm_mma_kernel, cudaFuncAttributeMaxDynamicSharedMemorySize, GEMM_SMEM);

    // weight packs (B side: hi|hi|lo) into merged layouts
    pack_b_kernel<<<(UPD * INP + 255) / 256, 256>>>(W_up_l, WupP, INP, UPD * INP);
    pack_b_kernel<<<(HID * INP + 255) / 256, 256>>>(W_up_r, WupP + (size_t)UPD * 3 * INP, INP, HID * INP);
    pack_b_kernel<<<(HID * UPD + 255) / 256, 256>>>(W_skip, WsfP, UPD, HID * UPD);
    pack_b_kernel<<<(FOUT * UPD + 255) / 256, 256>>>(fused_W, WsfP + (size_t)HID * 3 * UPD, UPD, FOUT * UPD);
    pack_b_kernel<<<(INP * HID + 255) / 256, 256>>>(W_down, WdP, HID, INP * HID);
    bias_build_kernel<<<(NSF + 255) / 256, 256>>>(fused_b, biasM);

    // LN1 + A-pack
    ln1_pack_kernel<<<ROWS, 256>>>(x, ln1_g, ln1_b, xnP);

    // merged up projection: [xt | rt] = xn @ [W_up_l; W_up_r]^T   (K3=2304)
    gemm_mma_kernel<<<dim3(NUP / 128, ROWS / 128), 256, GEMM_SMEM>>>(NUP, 3 * INP, xnP, WupP, nullptr, upM);

    // conv + silu + A-pack
    conv_silu_pack_kernel<<<(ROWS * UPD + 255) / 256, 256>>>(upM, conv_w, xcP);

    // merged skip+fused: [xskip | fused] = xc @ [W_skip; fused_W]^T   (K3=4608)
    gemm_mma_kernel<<<dim3((NSF + 127) / 128, ROWS / 128), 256, GEMM_SMEM>>>(NSF, 3 * UPD, xcP, WsfP, biasM, sfM);

    // sequential scan (e-split x2)
    float* outC = out + (size_t)ROWS * INP;
    float* outN = outC + (size_t)BATCH * NH * HD * HD;
    float* outM = outN + (size_t)BATCH * NH * HD;
    scan_kernel<<<BATCH * NH * 2, 96>>>(sfM, ht0, ht1, dp, outC, outN, outM);

    // post: o-gate + LN2 + A-pack
    post_pack_kernel<<<ROWS, 256>>>(sfM, ht0, ht1, dp, ln2_g, ln2_b, hn2P);

    // down projection (K3 = 2304)
    gemm_mma_kernel<<<dim3(HID / 128, ROWS / 128), 256, GEMM_SMEM>>>(HID, 3 * HID, hn2P, WdP, nullptr, y1);

    final_kernel<<<(ROWS * HID + 255) / 256, 256>>>(y1, sfM, upM, x, out);
}

// round 14
// speedup vs baseline: 2.3551x; 1.0264x over previous
#include <cuda_runtime.h>
#include <cuda_bf16.h>
#include <cstdint>

#define INP   768
#define HID   768
#define NH    8
#define HD    96
#define UPD   1536
#define FOUT  3088
#define BATCH 8
#define SEQ   1024
#define ROWS  (BATCH*SEQ)   /* 8192 */
#define CAPV  15.0f

#define NUP   (UPD + HID)          /* 2304 merged up-proj width  */
#define NSF   (HID + FOUT)         /* 3856 merged skip+fused width */
#define OFF_I (HID + 0)            /* 768  */
#define OFF_F (HID + 8)            /* 776  */
#define OFF_O (HID + 16)           /* 784  */
#define OFF_Q (HID + 784)          /* 1552 */
#define OFF_K (HID + 1552)         /* 2320 */
#define OFF_V (HID + 2320)         /* 3088 */

typedef unsigned long long ull;

// -------------------- scratch (no allocs allowed) --------------------
__device__ __align__(256) __nv_bfloat16 g_xnP  [ (size_t)ROWS*3*INP ];
__device__ __align__(256) __nv_bfloat16 g_xcP  [ (size_t)ROWS*3*UPD ];
__device__ __align__(256) __nv_bfloat16 g_hn2P [ (size_t)ROWS*3*HID ];
__device__ __align__(256) __nv_bfloat16 g_WupP [ (size_t)NUP*3*INP ];
__device__ __align__(256) __nv_bfloat16 g_WsfP [ (size_t)NSF*3*UPD ];
__device__ __align__(256) __nv_bfloat16 g_WdP  [ (size_t)INP*3*HID ];
__device__ __align__(256) float g_upM  [ (size_t)ROWS*NUP ];   // [xt | rt]
__device__ __align__(256) float g_sfM  [ (size_t)ROWS*NSF ];   // [xskip | fused]
__device__ __align__(256) float g_ht0  [ (size_t)ROWS*HID ];
__device__ __align__(256) float g_ht1  [ (size_t)ROWS*HID ];
__device__ __align__(256) float g_dp   [ (size_t)ROWS*HID ];
__device__ __align__(256) float g_y1   [ (size_t)ROWS*HID ];
__device__ __align__(256) float g_biasM[ NSF ];

// -------------------- packed f32x2 helpers --------------------
__device__ __forceinline__ ull ffma2(ull a, ull b, ull c) {
    ull d; asm("fma.rn.f32x2 %0, %1, %2, %3;" : "=l"(d) : "l"(a), "l"(b), "l"(c)); return d;
}
__device__ __forceinline__ ull fmul2(ull a, ull b) {
    ull d; asm("mul.rn.f32x2 %0, %1, %2;" : "=l"(d) : "l"(a), "l"(b)); return d;
}
__device__ __forceinline__ ull fadd2(ull a, ull b) {
    ull d; asm("add.rn.f32x2 %0, %1, %2;" : "=l"(d) : "l"(a), "l"(b)); return d;
}
__device__ __forceinline__ ull bcast2(float x) {
    ull d; asm("mov.b64 %0, {%1, %1};" : "=l"(d) : "f"(x)); return d;
}
__device__ __forceinline__ float2 unpack2(ull v) {
    float2 f; asm("mov.b64 {%0, %1}, %2;" : "=f"(f.x), "=f"(f.y) : "l"(v)); return f;
}

// -------------------- mma / ldmatrix / cp.async helpers --------------------
static __device__ __forceinline__ uint32_t smem_u32(const void* p) {
    uint32_t a;
    asm("{ .reg .u64 t; cvta.to.shared.u64 t, %1; cvt.u32.u64 %0, t; }" : "=r"(a) : "l"(p));
    return a;
}
#define LDSM4(r, addr) \
    asm volatile("ldmatrix.sync.aligned.m8n8.x4.shared.b16 {%0,%1,%2,%3}, [%4];" \
        : "=r"((r)[0]), "=r"((r)[1]), "=r"((r)[2]), "=r"((r)[3]) : "r"(addr))
#define MMA16816(c, a, b0, b1) \
    asm volatile("mma.sync.aligned.m16n8k16.row.col.f32.bf16.bf16.f32 " \
        "{%0,%1,%2,%3}, {%4,%5,%6,%7}, {%8,%9}, {%0,%1,%2,%3};" \
        : "+f"((c)[0]), "+f"((c)[1]), "+f"((c)[2]), "+f"((c)[3]) \
        : "r"((a)[0]), "r"((a)[1]), "r"((a)[2]), "r"((a)[3]), "r"(b0), "r"(b1))
static __device__ __forceinline__ void cp_async16(uint32_t d, const void* g, int sz) {
    asm volatile("cp.async.cg.shared.global [%0], [%1], 16, %2;"
                 :: "r"(d), "l"(g), "r"(sz) : "memory");
}
#define CP_COMMIT() asm volatile("cp.async.commit_group;" ::: "memory")
#define CP_WAIT1()  asm volatile("cp.async.wait_group 1;" ::: "memory")
#define CP_WAIT0()  asm volatile("cp.async.wait_group 0;" ::: "memory")

// 128B rows, 8 chunks of 16B, XOR-swizzled by row&7
static __device__ __forceinline__ uint32_t sw128(uint32_t base, int row, int ch) {
    return base + ((uint32_t)row << 7) + ((uint32_t)((ch ^ (row & 7)) & 7) << 4);
}

// -------------------- reduction helper --------------------
__device__ __forceinline__ void block_reduce_sum2(float& s, float& s2,
                                                  float* sh, float* sh2) {
    int lane = threadIdx.x & 31, wid = threadIdx.x >> 5;
#pragma unroll
    for (int o = 16; o > 0; o >>= 1) {
        s  += __shfl_xor_sync(0xffffffffu, s,  o);
        s2 += __shfl_xor_sync(0xffffffffu, s2, o);
    }
    if (lane == 0) { sh[wid] = s; sh2[wid] = s2; }
    __syncthreads();
    float t = 0.f, t2 = 0.f;
#pragma unroll
    for (int i = 0; i < 8; i++) { t += sh[i]; t2 += sh2[i]; }
    s = t; s2 = t2;
}

__device__ __forceinline__ void split_bf16(float x, __nv_bfloat16& hi, __nv_bfloat16& lo) {
    hi = __float2bfloat16(x);
    lo = __float2bfloat16(x - __bfloat162float(hi));
}
__device__ __forceinline__ uint32_t pack_hi2(float a, float b) {
    __nv_bfloat162 h = __floats2bfloat162_rn(a, b);
    return *(uint32_t*)&h;
}

// -------------------- LayerNorm over 768 + A-pack write --------------------
__global__ __launch_bounds__(256) void ln1_pack_kernel(const float* __restrict__ x,
                                                       const float* __restrict__ g,
                                                       const float* __restrict__ b,
                                                       __nv_bfloat16* __restrict__ p) {
    __shared__ float sh[8], sh2[8];
    int row = blockIdx.x, t = threadIdx.x;
    const float* xr = x + (size_t)row * INP;
    float v0 = xr[t], v1 = xr[t + 256], v2 = xr[t + 512];
    float s = v0 + v1 + v2;
    float s2 = v0 * v0 + v1 * v1 + v2 * v2;
    block_reduce_sum2(s, s2, sh, sh2);
    float mean = s * (1.0f / INP);
    float var  = s2 * (1.0f / INP) - mean * mean;
    float r = rsqrtf(var + 1e-6f);
    __nv_bfloat16* pr = p + (size_t)row * 3 * INP;
#pragma unroll
    for (int k = 0; k < 3; k++) {
        int j = t + k * 256;
        float v = (k == 0) ? v0 : (k == 1) ? v1 : v2;
        float y = (v - mean) * r * g[j] + b[j];
        __nv_bfloat16 hi, lo; split_bf16(y, hi, lo);
        pr[j] = hi; pr[INP + j] = lo; pr[2 * INP + j] = hi;
    }
}

// -------------------- weight B-pack: [hi | hi | lo] --------------------
__global__ void pack_b_kernel(const float* __restrict__ src,
                              __nv_bfloat16* __restrict__ dst,
                              int K, int total) {
    int i = blockIdx.x * blockDim.x + threadIdx.x;
    if (i >= total) return;
    int row = i / K, j = i % K;
    float x = src[i];
    __nv_bfloat16 hi, lo; split_bf16(x, hi, lo);
    __nv_bfloat16* d = dst + (size_t)row * 3 * K;
    d[j] = hi; d[K + j] = hi; d[2 * K + j] = lo;
}

__global__ void bias_build_kernel(const float* __restrict__ fb, float* __restrict__ bm) {
    int i = blockIdx.x * blockDim.x + threadIdx.x;
    if (i >= NSF) return;
    bm[i] = (i < HID) ? 0.f : fb[i - HID];
}

// -------------------- warp-MMA bf16 NT GEMM, K64 tiles, 3-stage cp.async ------------
// 128 thr = 4 warps (2x2); block tile 128x128; warp tile 64x64; dyn smem 96KB.
__global__ __launch_bounds__(128) void gemm_mma_kernel(
    int Nn, int K3,
    const __nv_bfloat16* __restrict__ A, const __nv_bfloat16* __restrict__ B,
    const float* __restrict__ bias, float* __restrict__ Cout) {
    extern __shared__ __align__(1024) char sm[];
    uint32_t sA = smem_u32(sm);            // 3 x 16KB
    uint32_t sB = sA + 49152u;             // 3 x 16KB
    int tid = threadIdx.x;
    int bm = blockIdx.y * 128, bn = blockIdx.x * 128;
    int wid = tid >> 5, lane = tid & 31;
    int wm = wid >> 1, wn = wid & 1;
    int lr = lane & 7, grp = lane >> 3;
    int niter = K3 >> 6;

    float acc[4][8][4];   // [fm][np*2+fl][quad]
#pragma unroll
    for (int i = 0; i < 4; i++)
#pragma unroll
        for (int j = 0; j < 8; j++)
#pragma unroll
            for (int q = 0; q < 4; q++) acc[i][j][q] = 0.f;

    auto issue_stage = [&](int it, int s) {
        int kt = it << 6;
#pragma unroll
        for (int q = 0; q < 8; q++) {
            int idx = tid + q * 128;          // 1024 = 128 rows x 8 ch
            int r = idx >> 3, ch = idx & 7;
            cp_async16(sw128(sA + (uint32_t)s * 16384u, r, ch),
                       A + (size_t)(bm + r) * K3 + kt + ch * 8, 16);
        }
#pragma unroll
        for (int q = 0; q < 8; q++) {
            int idx = tid + q * 128;
            int r = idx >> 3, ch = idx & 7;
            int br = bn + r;
            cp_async16(sw128(sB + (uint32_t)s * 16384u, r, ch),
                       B + (size_t)(br < Nn ? br : 0) * K3 + kt + ch * 8,
                       br < Nn ? 16 : 0);
        }
        CP_COMMIT();
    };

    issue_stage(0, 0);
    if (niter > 1) issue_stage(1, 1);

    for (int it = 0; it < niter; it++) {
        int s = it % 3;
        if (it + 1 < niter) CP_WAIT1(); else CP_WAIT0();
        __syncthreads();

        uint32_t Ab = sA + (uint32_t)s * 16384u;
        uint32_t Bb = sB + (uint32_t)s * 16384u;
#pragma unroll
        for (int ks = 0; ks < 4; ks++) {
            uint32_t a[4][4];
#pragma unroll
            for (int fm = 0; fm < 4; fm++) {
                int row = wm * 64 + fm * 16 + lr + ((grp & 1) << 3);
                int ch = ks * 2 + (grp >> 1);
                LDSM4(a[fm], sw128(Ab, row, ch));
            }
            uint32_t b[4][4];
#pragma unroll
            for (int np = 0; np < 4; np++) {
                int row = wn * 64 + np * 16 + lr + ((grp >> 1) << 3);
                int ch = ks * 2 + (grp & 1);
                LDSM4(b[np], sw128(Bb, row, ch));
            }
#pragma unroll
            for (int fm = 0; fm < 4; fm++)
#pragma unroll
                for (int np = 0; np < 4; np++) {
#pragma unroll
                    for (int fl = 0; fl < 2; fl++)
                        MMA16816(acc[fm][np * 2 + fl], a[fm], b[np][fl * 2], b[np][fl * 2 + 1]);
                }
        }
        if (it + 2 < niter) issue_stage(it + 2, (it + 2) % 3);
    }

    int qr = lane >> 2, qc = lane & 3;
#pragma unroll
    for (int fn = 0; fn < 8; fn++) {
        int np = fn >> 1, fl = fn & 1;
        int col = bn + wn * 64 + np * 16 + fl * 8 + qc * 2;
        if (col < Nn) {
            float bx = bias ? bias[col] : 0.f;
            float by = bias ? bias[col + 1] : 0.f;
#pragma unroll
            for (int fm = 0; fm < 4; fm++) {
                int row0 = bm + wm * 64 + fm * 16 + qr;
                float2 v0 = make_float2(acc[fm][fn][0] + bx, acc[fm][fn][1] + by);
                float2 v1 = make_float2(acc[fm][fn][2] + bx, acc[fm][fn][3] + by);
                *(float2*)(Cout + (size_t)row0 * Nn + col) = v0;
                *(float2*)(Cout + (size_t)(row0 + 8) * Nn + col) = v1;
            }
        }
    }
}

// -------------------- causal conv + silu + A-pack, float4 per thread --------------------
// grid (UPD/512, ROWS), 128 threads, 4 elems each
__global__ __launch_bounds__(128) void conv_silu_pack_kernel(const float* __restrict__ up,
                                                             const float* __restrict__ w,
                                                             __nv_bfloat16* __restrict__ p) {
    int row = blockIdx.y;
    int j = (blockIdx.x * 128 + threadIdx.x) * 4;
    const float* xr = up + (size_t)row * NUP;
    float4 v = *(const float4*)(xr + j);
    float p0 = 0.f, p1 = 0.f, p2 = 0.f;      // xr[j-1], xr[j-2], xr[j-3]
    if (j >= 4) {
        float4 pv = *(const float4*)(xr + j - 4);
        p0 = pv.w; p1 = pv.z; p2 = pv.y;
    }
    float w0 = w[0], w1 = w[1], w2 = w[2], w3 = w[3];
    float o0 = w3 * v.x + w2 * p0 + w1 * p1 + w0 * p2;
    float o1 = w3 * v.y + w2 * v.x + w1 * p0 + w0 * p1;
    float o2 = w3 * v.z + w2 * v.y + w1 * v.x + w0 * p0;
    float o3 = w3 * v.w + w2 * v.z + w1 * v.y + w0 * v.x;
    o0 = o0 / (1.0f + expf(-o0));
    o1 = o1 / (1.0f + expf(-o1));
    o2 = o2 / (1.0f + expf(-o2));
    o3 = o3 / (1.0f + expf(-o3));
    __nv_bfloat16 h0, l0, h1, l1, h2, l2, h3, l3;
    split_bf16(o0, h0, l0); split_bf16(o1, h1, l1);
    split_bf16(o2, h2, l2); split_bf16(o3, h3, l3);
    __nv_bfloat16* pr = p + (size_t)row * 3 * UPD;
    uint2 hv = make_uint2(pack_hi2(o0, o1), pack_hi2(o2, o3));
    *(uint2*)(pr + j) = hv;
    *(uint2*)(pr + 2 * UPD + j) = hv;
    uint2 lv;
    { __nv_bfloat162 t0; t0.x = l0; t0.y = l1; lv.x = *(uint32_t*)&t0;
      __nv_bfloat162 t1; t1.x = l2; t1.y = l3; lv.y = *(uint32_t*)&t1; }
    *(uint2*)(pr + UPD + j) = lv;
}

// -------------------- sequential mLSTM scan: 2 blocks per (b,h), e-split --------------------
__global__ __launch_bounds__(96) void scan_kernel(const float* __restrict__ sf,
                                                  float* __restrict__ ht0,
                                                  float* __restrict__ ht1,
                                                  float* __restrict__ dpo,
                                                  float* __restrict__ outC,
                                                  float* __restrict__ outN,
                                                  float* __restrict__ outM) {
    int bx = blockIdx.x;
    int bh = bx >> 1, sp = bx & 1;
    int b = bh >> 3, h = bh & 7;
    int e0 = sp * 48;
    int t = threadIdx.x;          // d = row of C
    const float inv = rsqrtf((float)HD);

    ull C[24];                    // e-range [e0, e0+48) as packed pairs
#pragma unroll
    for (int e = 0; e < 24; e++) C[e] = 0ull;
    float nd = 1.0f, m = 0.0f;

    __shared__ __align__(16) float qs[2][48];
    __shared__ __align__(16) float ks[2][48];

    const float* base = sf + (size_t)b * SEQ * NSF;
    float* htp = sp ? ht1 : ht0;

    float qv = 0.f, kv = 0.f;
    if (t < 48) {
        qv = base[OFF_Q + h * HD + e0 + t];
        kv = base[OFF_K + h * HD + e0 + t];
    }
    float vv = base[OFF_V + h * HD + t];
    float iv = base[OFF_I + h];
    float fv = base[OFF_F + h];

    for (int s = 0; s < SEQ; s++) {
        int p = s & 1;
        float qd = qv, kd = kv * inv, vd = vv;
        float i_t = CAPV * tanhf(iv * (1.0f / CAPV));
        float f_t = CAPV * tanhf(fv * (1.0f / CAPV));
        if (t < 48) { qs[p][t] = qd; ks[p][t] = kd; }
        __syncthreads();

        if (s + 1 < SEQ) {
            const float* b2 = base + (size_t)(s + 1) * NSF;
            if (t < 48) {
                qv = b2[OFF_Q + h * HD + e0 + t];
                kv = b2[OFF_K + h * HD + e0 + t];
            }
            vv = b2[OFF_V + h * HD + t];
            iv = b2[OFF_I + h];
            fv = b2[OFF_F + h];
        }

        float m_t = fmaxf(f_t + m, i_t);
        float ie = expf(i_t - m_t);
        float fe = expf(f_t - m_t + m);
        m = m_t;

        ull pa  = bcast2(ie * vd);
        ull pfe = bcast2(fe);
        const ulonglong2* kp2 = (const ulonglong2*)ks[p];
        const ulonglong2* qp2 = (const ulonglong2*)qs[p];
        ull hn0 = 0ull, hn1 = 0ull, hn2a = 0ull, hn3 = 0ull;
#pragma unroll
        for (int e2 = 0; e2 < 12; e2 += 2) {
            ulonglong2 kk0 = kp2[e2],     qq0 = qp2[e2];
            ulonglong2 kk1 = kp2[e2 + 1], qq1 = qp2[e2 + 1];
            ull c;
            c = ffma2(pa, kk0.x, fmul2(pfe, C[2 * e2 + 0])); C[2 * e2 + 0] = c; hn0  = ffma2(c, qq0.x, hn0);
            c = ffma2(pa, kk0.y, fmul2(pfe, C[2 * e2 + 1])); C[2 * e2 + 1] = c; hn1  = ffma2(c, qq0.y, hn1);
            c = ffma2(pa, kk1.x, fmul2(pfe, C[2 * e2 + 2])); C[2 * e2 + 2] = c; hn2a = ffma2(c, qq1.x, hn2a);
            c = ffma2(pa, kk1.y, fmul2(pfe, C[2 * e2 + 3])); C[2 * e2 + 3] = c; hn3  = ffma2(c, qq1.y, hn3);
        }
        float2 hf = unpack2(fadd2(fadd2(hn0, hn1), fadd2(hn2a, hn3)));
        float hnv = hf.x + hf.y;

        size_t o = ((size_t)b * SEQ + s) * HID + h * HD;
        htp[o + t] = hnv;               // partial over e-range
        if (t < 48) {
            nd = fmaf(ie, kd, fe * nd);
            dpo[o + e0 + t] = nd * qd;  // disjoint d across the two splits
        }
    }

    // final state outputs
    float* Cr = outC + ((size_t)bh * HD + t) * HD + e0;
#pragma unroll
    for (int e = 0; e < 24; e++) {
        float2 f = unpack2(C[e]);
        *(float2*)(Cr + 2 * e) = f;
    }
    if (t < 48) outN[bh * HD + e0 + t] = nd;
    if (sp == 0 && t == 0) outM[bh] = m;
}

// -------------------- denom reduce + o-gate, LN2, A-pack write --------------------
__global__ __launch_bounds__(256) void post_pack_kernel(const float* __restrict__ sf,
                                                        const float* __restrict__ ht0,
                                                        const float* __restrict__ ht1,
                                                        const float* __restrict__ dp,
                                                        const float* __restrict__ g,
                                                        const float* __restrict__ b,
                                                        __nv_bfloat16* __restrict__ p) {
    __shared__ float sh[8], sh2[8], sden[8];
    int row = blockIdx.x, t = threadIdx.x;
    int w = t >> 5, lane = t & 31;

    const float* dpr = dp + (size_t)row * HID;
    float sdp = dpr[w * 96 + lane] + dpr[w * 96 + 32 + lane] + dpr[w * 96 + 64 + lane];
#pragma unroll
    for (int o = 16; o > 0; o >>= 1) sdp += __shfl_xor_sync(0xffffffffu, sdp, o);
    if (lane == 0) sden[w] = fmaxf(sdp, 1.0f);
    __syncthreads();

    const float* fr = sf + (size_t)row * NSF + OFF_O;
    const float* h0 = ht0 + (size_t)row * HID;
    const float* h1 = ht1 + (size_t)row * HID;
    float hv[3]; float s = 0.f, s2 = 0.f;
#pragma unroll
    for (int k = 0; k < 3; k++) {
        int j = t + k * 256;
        float oraw = fr[j];
        float og = 1.0f / (1.0f + expf(-CAPV * tanhf(oraw * (1.0f / CAPV))));
        float h = og * ((h0[j] + h1[j]) / sden[j / 96]);
        hv[k] = h; s += h; s2 += h * h;
    }
    block_reduce_sum2(s, s2, sh, sh2);
    float mean = s * (1.0f / HID);
    float var  = s2 * (1.0f / HID) - mean * mean;
    float r = rsqrtf(var + 1e-6f);
    __nv_bfloat16* pr = p + (size_t)row * 3 * HID;
#pragma unroll
    for (int k = 0; k < 3; k++) {
        int j = t + k * 256;
        float y = (hv[k] - mean) * r * g[j] + b[j];
        __nv_bfloat16 hi, lo; split_bf16(y, hi, lo);
        pr[j] = hi; pr[HID + j] = lo; pr[2 * HID + j] = hi;
    }
}

// -------------------- final fuse: (y1 + xskip)*silu(rt) + x, float4 --------------------
__global__ __launch_bounds__(192) void final_kernel(const float* __restrict__ y1,
                                                    const float* __restrict__ sf,
                                                    const float* __restrict__ up,
                                                    const float* __restrict__ x,
                                                    float* __restrict__ out) {
    int row = blockIdx.x;
    int j = threadIdx.x * 4;
    float4 yv = *(const float4*)(y1 + (size_t)row * HID + j);
    float4 sk = *(const float4*)(sf + (size_t)row * NSF + j);
    float4 rv = *(const float4*)(up + (size_t)row * NUP + UPD + j);
    float4 xv = *(const float4*)(x + (size_t)row * HID + j);
    float4 o;
    o.x = (yv.x + sk.x) * (rv.x / (1.0f + expf(-rv.x))) + xv.x;
    o.y = (yv.y + sk.y) * (rv.y / (1.0f + expf(-rv.y))) + xv.y;
    o.z = (yv.z + sk.z) * (rv.z / (1.0f + expf(-rv.z))) + xv.z;
    o.w = (yv.w + sk.w) * (rv.w / (1.0f + expf(-rv.w))) + xv.w;
    *(float4*)(out + (size_t)row * HID + j) = o;
}

// -------------------- launch --------------------
#define GEMM_SMEM (3 * 32768)

extern "C" void kernel_launch(void* const* d_in, const int* in_sizes, int n_in,
                              void* d_out, int out_size) {
    (void)in_sizes; (void)n_in; (void)out_size;
    const float* x       = (const float*)d_in[0];
    const float* ln1_g   = (const float*)d_in[1];
    const float* ln1_b   = (const float*)d_in[2];
    const float* W_up_l  = (const float*)d_in[3];
    const float* W_up_r  = (const float*)d_in[4];
    const float* conv_w  = (const float*)d_in[5];
    const float* W_skip  = (const float*)d_in[6];
    const float* fused_W = (const float*)d_in[7];
    const float* fused_b = (const float*)d_in[8];
    const float* ln2_g   = (const float*)d_in[9];
    const float* ln2_b   = (const float*)d_in[10];
    const float* W_down  = (const float*)d_in[11];
    float* out = (float*)d_out;

    __nv_bfloat16 *xnP, *xcP, *hn2P, *WupP, *WsfP, *WdP;
    float *upM, *sfM, *ht0, *ht1, *dp, *y1, *biasM;
    cudaGetSymbolAddress((void**)&xnP,   g_xnP);
    cudaGetSymbolAddress((void**)&xcP,   g_xcP);
    cudaGetSymbolAddress((void**)&hn2P,  g_hn2P);
    cudaGetSymbolAddress((void**)&WupP,  g_WupP);
    cudaGetSymbolAddress((void**)&WsfP,  g_WsfP);
    cudaGetSymbolAddress((void**)&WdP,   g_WdP);
    cudaGetSymbolAddress((void**)&upM,   g_upM);
    cudaGetSymbolAddress((void**)&sfM,   g_sfM);
    cudaGetSymbolAddress((void**)&ht0,   g_ht0);
    cudaGetSymbolAddress((void**)&ht1,   g_ht1);
    cudaGetSymbolAddress((void**)&dp,    g_dp);
    cudaGetSymbolAddress((void**)&y1,    g_y1);
    cudaGetSymbolAddress((void**)&biasM, g_biasM);

    cudaFuncSetAttribute(gemm_mma_kernel, cudaFuncAttributeMaxDynamicSharedMemorySize, GEMM_SMEM);

    // launches ordered so launch #5 is the up-GEMM (ncu -s 5 -c 1 profiles it)
    ln1_pack_kernel<<<ROWS, 256>>>(x, ln1_g, ln1_b, xnP);                                     // 0
    pack_b_kernel<<<(UPD * INP + 255) / 256, 256>>>(W_up_l, WupP, INP, UPD * INP);            // 1
    pack_b_kernel<<<(HID * INP + 255) / 256, 256>>>(W_up_r, WupP + (size_t)UPD * 3 * INP, INP, HID * INP); // 2
    pack_b_kernel<<<(HID * UPD + 255) / 256, 256>>>(W_skip, WsfP, UPD, HID * UPD);            // 3
    pack_b_kernel<<<(FOUT * UPD + 255) / 256, 256>>>(fused_W, WsfP + (size_t)HID * 3 * UPD, UPD, FOUT * UPD); // 4

    // merged up projection: [xt | rt] = xn @ [W_up_l; W_up_r]^T   (K3=2304)
    gemm_mma_kernel<<<dim3(NUP / 128, ROWS / 128), 128, GEMM_SMEM>>>(NUP, 3 * INP, xnP, WupP, nullptr, upM); // 5

    bias_build_kernel<<<(NSF + 255) / 256, 256>>>(fused_b, biasM);                            // 6
    conv_silu_pack_kernel<<<dim3(UPD / 512, ROWS), 128>>>(upM, conv_w, xcP);                  // 7

    // merged skip+fused: [xskip | fused] = xc @ [W_skip; fused_W]^T   (K3=4608)
    gemm_mma_kernel<<<dim3((NSF + 127) / 128, ROWS / 128), 128, GEMM_SMEM>>>(NSF, 3 * UPD, xcP, WsfP, biasM, sfM); // 8

    // sequential scan (e-split x2)
    float* outC = out + (size_t)ROWS * INP;
    float* outN = outC + (size_t)BATCH * NH * HD * HD;
    float* outM = outN + (size_t)BATCH * NH * HD;
    scan_kernel<<<BATCH * NH * 2, 96>>>(sfM, ht0, ht1, dp, outC, outN, outM);                 // 9

    post_pack_kernel<<<ROWS, 256>>>(sfM, ht0, ht1, dp, ln2_g, ln2_b, hn2P);                   // 10
    pack_b_kernel<<<(INP * HID + 255) / 256, 256>>>(W_down, WdP, HID, INP * HID);             // 11

    // down projection (K3 = 2304)
    gemm_mma_kernel<<<dim3(HID / 128, ROWS / 128), 128, GEMM_SMEM>>>(HID, 3 * HID, hn2P, WdP, nullptr, y1); // 12

    final_kernel<<<ROWS, 192>>>(y1, sfM, upM, x, out);                                        // 13
}

// round 15
// speedup vs baseline: 2.4140x; 1.0250x over previous
#include <cuda_runtime.h>
#include <cuda_bf16.h>
#include <cuda_fp16.h>
#include <cstdint>

#define INP   768
#define HID   768
#define NH    8
#define HD    96
#define UPD   1536
#define FOUT  3088
#define BATCH 8
#define SEQ   1024
#define ROWS  (BATCH*SEQ)   /* 8192 */
#define CAPV  15.0f

#define NUP   (UPD + HID)          /* 2304 merged up-proj width  */
#define NSF   (HID + FOUT)         /* 3856 merged skip+fused width */
#define OFF_O (HID + 16)           /* 784  */
#define OFF_Q (HID + 784)          /* 1552 */
#define OFF_K (HID + 1552)         /* 2320 */
#define OFF_V (HID + 2320)         /* 3088 */

typedef unsigned long long ull;

// -------------------- scratch (no allocs allowed) --------------------
__device__ __align__(256) __nv_bfloat16 g_xnP  [ (size_t)ROWS*3*INP ];   // bf16 [hi|lo|hi]
__device__ __align__(256) __half        g_xcP  [ (size_t)ROWS*2*UPD ];   // fp16 [hi|lo]
__device__ __align__(256) __half        g_hn2P [ (size_t)ROWS*2*HID ];   // fp16 [hi|lo]
__device__ __align__(256) __nv_bfloat16 g_WupP [ (size_t)NUP*3*INP ];    // bf16 [hi|hi|lo]
__device__ __align__(256) __half        g_WsfP [ (size_t)NSF*2*UPD ];    // fp16 [hi|hi]
__device__ __align__(256) __half        g_WdP  [ (size_t)INP*2*HID ];    // fp16 [hi|hi]
__device__ __align__(256) float g_upM  [ (size_t)ROWS*NUP ];   // [xt | rt]
__device__ __align__(256) float g_sfM  [ (size_t)ROWS*NSF ];   // [xskip | fused]
__device__ __align__(256) float g_ht0  [ (size_t)ROWS*HID ];
__device__ __align__(256) float g_ht1  [ (size_t)ROWS*HID ];
__device__ __align__(256) float g_dp   [ (size_t)ROWS*HID ];
__device__ __align__(256) float g_y1   [ (size_t)ROWS*HID ];
__device__ __align__(256) float g_biasM[ NSF ];
__device__ __align__(256) float g_if   [ (size_t)ROWS*16 ];   // soft-capped i(8)|f(8) per row
__device__ __align__(256) float g_ie   [ (size_t)ROWS*NH ];
__device__ __align__(256) float g_fe   [ (size_t)ROWS*NH ];

// -------------------- packed f32x2 helpers --------------------
__device__ __forceinline__ ull ffma2(ull a, ull b, ull c) {
    ull d; asm("fma.rn.f32x2 %0, %1, %2, %3;" : "=l"(d) : "l"(a), "l"(b), "l"(c)); return d;
}
__device__ __forceinline__ ull fmul2(ull a, ull b) {
    ull d; asm("mul.rn.f32x2 %0, %1, %2;" : "=l"(d) : "l"(a), "l"(b)); return d;
}
__device__ __forceinline__ ull fadd2(ull a, ull b) {
    ull d; asm("add.rn.f32x2 %0, %1, %2;" : "=l"(d) : "l"(a), "l"(b)); return d;
}
__device__ __forceinline__ ull bcast2(float x) {
    ull d; asm("mov.b64 %0, {%1, %1};" : "=l"(d) : "f"(x)); return d;
}
__device__ __forceinline__ float2 unpack2(ull v) {
    float2 f; asm("mov.b64 {%0, %1}, %2;" : "=f"(f.x), "=f"(f.y) : "l"(v)); return f;
}

// -------------------- mma / ldmatrix / cp.async helpers --------------------
static __device__ __forceinline__ uint32_t smem_u32(const void* p) {
    uint32_t a;
    asm("{ .reg .u64 t; cvta.to.shared.u64 t, %1; cvt.u32.u64 %0, t; }" : "=r"(a) : "l"(p));
    return a;
}
#define LDSM4(r, addr) \
    asm volatile("ldmatrix.sync.aligned.m8n8.x4.shared.b16 {%0,%1,%2,%3}, [%4];" \
        : "=r"((r)[0]), "=r"((r)[1]), "=r"((r)[2]), "=r"((r)[3]) : "r"(addr))
#define MMA_BF16(c, a, b0, b1) \
    asm volatile("mma.sync.aligned.m16n8k16.row.col.f32.bf16.bf16.f32 " \
        "{%0,%1,%2,%3}, {%4,%5,%6,%7}, {%8,%9}, {%0,%1,%2,%3};" \
        : "+f"((c)[0]), "+f"((c)[1]), "+f"((c)[2]), "+f"((c)[3]) \
        : "r"((a)[0]), "r"((a)[1]), "r"((a)[2]), "r"((a)[3]), "r"(b0), "r"(b1))
#define MMA_F16(c, a, b0, b1) \
    asm volatile("mma.sync.aligned.m16n8k16.row.col.f32.f16.f16.f32 " \
        "{%0,%1,%2,%3}, {%4,%5,%6,%7}, {%8,%9}, {%0,%1,%2,%3};" \
        : "+f"((c)[0]), "+f"((c)[1]), "+f"((c)[2]), "+f"((c)[3]) \
        : "r"((a)[0]), "r"((a)[1]), "r"((a)[2]), "r"((a)[3]), "r"(b0), "r"(b1))
static __device__ __forceinline__ void cp_async16(uint32_t d, const void* g, int sz) {
    asm volatile("cp.async.cg.shared.global [%0], [%1], 16, %2;"
                 :: "r"(d), "l"(g), "r"(sz) : "memory");
}
#define CP_COMMIT() asm volatile("cp.async.commit_group;" ::: "memory")
#define CP_WAIT1()  asm volatile("cp.async.wait_group 1;" ::: "memory")
#define CP_WAIT0()  asm volatile("cp.async.wait_group 0;" ::: "memory")

// 128B rows, 8 chunks of 16B, XOR-swizzled by row&7
static __device__ __forceinline__ uint32_t sw128(uint32_t base, int row, int ch) {
    return base + ((uint32_t)row << 7) + ((uint32_t)((ch ^ (row & 7)) & 7) << 4);
}

// -------------------- reduction helper --------------------
__device__ __forceinline__ void block_reduce_sum2(float& s, float& s2,
                                                  float* sh, float* sh2) {
    int lane = threadIdx.x & 31, wid = threadIdx.x >> 5;
#pragma unroll
    for (int o = 16; o > 0; o >>= 1) {
        s  += __shfl_xor_sync(0xffffffffu, s,  o);
        s2 += __shfl_xor_sync(0xffffffffu, s2, o);
    }
    if (lane == 0) { sh[wid] = s; sh2[wid] = s2; }
    __syncthreads();
    float t = 0.f, t2 = 0.f;
#pragma unroll
    for (int i = 0; i < 8; i++) { t += sh[i]; t2 += sh2[i]; }
    s = t; s2 = t2;
}

__device__ __forceinline__ void split_bf16(float x, __nv_bfloat16& hi, __nv_bfloat16& lo) {
    hi = __float2bfloat16(x);
    lo = __float2bfloat16(x - __bfloat162float(hi));
}
__device__ __forceinline__ void split_f16(float x, __half& hi, __half& lo) {
    hi = __float2half(x);
    lo = __float2half(x - __half2float(hi));
}

// -------------------- LayerNorm over 768 + bf16 3-term A-pack --------------------
__global__ __launch_bounds__(256) void ln1_pack_kernel(const float* __restrict__ x,
                                                       const float* __restrict__ g,
                                                       const float* __restrict__ b,
                                                       __nv_bfloat16* __restrict__ p) {
    __shared__ float sh[8], sh2[8];
    int row = blockIdx.x, t = threadIdx.x;
    const float* xr = x + (size_t)row * INP;
    float v0 = xr[t], v1 = xr[t + 256], v2 = xr[t + 512];
    float s = v0 + v1 + v2;
    float s2 = v0 * v0 + v1 * v1 + v2 * v2;
    block_reduce_sum2(s, s2, sh, sh2);
    float mean = s * (1.0f / INP);
    float var  = s2 * (1.0f / INP) - mean * mean;
    float r = rsqrtf(var + 1e-6f);
    __nv_bfloat16* pr = p + (size_t)row * 3 * INP;
#pragma unroll
    for (int k = 0; k < 3; k++) {
        int j = t + k * 256;
        float v = (k == 0) ? v0 : (k == 1) ? v1 : v2;
        float y = (v - mean) * r * g[j] + b[j];
        __nv_bfloat16 hi, lo; split_bf16(y, hi, lo);
        pr[j] = hi; pr[INP + j] = lo; pr[2 * INP + j] = hi;
    }
}

// -------------------- weight packs --------------------
__global__ void pack_b3_kernel(const float* __restrict__ src,
                               __nv_bfloat16* __restrict__ dst,
                               int K, int total) {         // bf16 [hi|hi|lo]
    int i = blockIdx.x * blockDim.x + threadIdx.x;
    if (i >= total) return;
    int row = i / K, j = i % K;
    __nv_bfloat16 hi, lo; split_bf16(src[i], hi, lo);
    __nv_bfloat16* d = dst + (size_t)row * 3 * K;
    d[j] = hi; d[K + j] = hi; d[2 * K + j] = lo;
}
__global__ void pack_b2_kernel(const float* __restrict__ src,
                               __half* __restrict__ dst,
                               int K, int total) {         // fp16 [hi|hi]
    int i = blockIdx.x * blockDim.x + threadIdx.x;
    if (i >= total) return;
    int row = i / K, j = i % K;
    __half hi = __float2half(src[i]);
    __half* d = dst + (size_t)row * 2 * K;
    d[j] = hi; d[K + j] = hi;
}

__global__ void bias_build_kernel(const float* __restrict__ fb, float* __restrict__ bm) {
    int i = blockIdx.x * blockDim.x + threadIdx.x;
    if (i >= NSF) return;
    bm[i] = (i < HID) ? 0.f : fb[i - HID];
}

// -------------------- warp-MMA NT GEMM, K64 tiles, 3-stage cp.async ------------
// 128 thr = 4 warps (2x2); block tile 128x128; warp tile 64x64; dyn smem 96KB.
template<int FP16>
__global__ __launch_bounds__(128) void gemm_mma_kernel(
    int Nn, int Kp,
    const void* __restrict__ Av, const void* __restrict__ Bv,
    const float* __restrict__ bias, float* __restrict__ Cout) {
    const __half* A = (const __half*)Av;      // 16-bit payload; dtype via FP16 flag
    const __half* B = (const __half*)Bv;
    extern __shared__ __align__(1024) char sm[];
    uint32_t sA = smem_u32(sm);            // 3 x 16KB
    uint32_t sB = sA + 49152u;             // 3 x 16KB
    int tid = threadIdx.x;
    int bm = blockIdx.y * 128, bn = blockIdx.x * 128;
    int wid = tid >> 5, lane = tid & 31;
    int wm = wid >> 1, wn = wid & 1;
    int lr = lane & 7, grp = lane >> 3;
    int niter = Kp >> 6;

    float acc[4][8][4];
#pragma unroll
    for (int i = 0; i < 4; i++)
#pragma unroll
        for (int j = 0; j < 8; j++)
#pragma unroll
            for (int q = 0; q < 4; q++) acc[i][j][q] = 0.f;

    auto issue_stage = [&](int it, int s) {
        int kt = it << 6;
#pragma unroll
        for (int q = 0; q < 8; q++) {
            int idx = tid + q * 128;
            int r = idx >> 3, ch = idx & 7;
            cp_async16(sw128(sA + (uint32_t)s * 16384u, r, ch),
                       A + (size_t)(bm + r) * Kp + kt + ch * 8, 16);
        }
#pragma unroll
        for (int q = 0; q < 8; q++) {
            int idx = tid + q * 128;
            int r = idx >> 3, ch = idx & 7;
            int br = bn + r;
            cp_async16(sw128(sB + (uint32_t)s * 16384u, r, ch),
                       B + (size_t)(br < Nn ? br : 0) * Kp + kt + ch * 8,
                       br < Nn ? 16 : 0);
        }
        CP_COMMIT();
    };

    issue_stage(0, 0);
    if (niter > 1) issue_stage(1, 1);

    for (int it = 0; it < niter; it++) {
        int s = it % 3;
        if (it + 1 < niter) CP_WAIT1(); else CP_WAIT0();
        __syncthreads();

        uint32_t Ab = sA + (uint32_t)s * 16384u;
        uint32_t Bb = sB + (uint32_t)s * 16384u;
#pragma unroll
        for (int ks = 0; ks < 4; ks++) {
            uint32_t a[4][4];
#pragma unroll
            for (int fm = 0; fm < 4; fm++) {
                int row = wm * 64 + fm * 16 + lr + ((grp & 1) << 3);
                int ch = ks * 2 + (grp >> 1);
                LDSM4(a[fm], sw128(Ab, row, ch));
            }
            uint32_t b[4][4];
#pragma unroll
            for (int np = 0; np < 4; np++) {
                int row = wn * 64 + np * 16 + lr + ((grp >> 1) << 3);
                int ch = ks * 2 + (grp & 1);
                LDSM4(b[np], sw128(Bb, row, ch));
            }
#pragma unroll
            for (int fm = 0; fm < 4; fm++)
#pragma unroll
                for (int np = 0; np < 4; np++) {
#pragma unroll
                    for (int fl = 0; fl < 2; fl++) {
                        if (FP16) { MMA_F16(acc[fm][np * 2 + fl], a[fm], b[np][fl * 2], b[np][fl * 2 + 1]); }
                        else      { MMA_BF16(acc[fm][np * 2 + fl], a[fm], b[np][fl * 2], b[np][fl * 2 + 1]); }
                    }
                }
        }
        if (it + 2 < niter) issue_stage(it + 2, (it + 2) % 3);
    }

    int qr = lane >> 2, qc = lane & 3;
#pragma unroll
    for (int fn = 0; fn < 8; fn++) {
        int np = fn >> 1, fl = fn & 1;
        int col = bn + wn * 64 + np * 16 + fl * 8 + qc * 2;
        if (col < Nn) {
            float bx = bias ? bias[col] : 0.f;
            float by = bias ? bias[col + 1] : 0.f;
#pragma unroll
            for (int fm = 0; fm < 4; fm++) {
                int row0 = bm + wm * 64 + fm * 16 + qr;
                float2 v0 = make_float2(acc[fm][fn][0] + bx, acc[fm][fn][1] + by);
                float2 v1 = make_float2(acc[fm][fn][2] + bx, acc[fm][fn][3] + by);
                *(float2*)(Cout + (size_t)row0 * Nn + col) = v0;
                *(float2*)(Cout + (size_t)(row0 + 8) * Nn + col) = v1;
            }
        }
    }
}

// -------------------- causal conv + silu + fp16 2-term A-pack, float4/thread ---------
__global__ __launch_bounds__(128) void conv_silu_pack_kernel(const float* __restrict__ up,
                                                             const float* __restrict__ w,
                                                             __half* __restrict__ p) {
    int row = blockIdx.y;
    int j = (blockIdx.x * 128 + threadIdx.x) * 4;
    const float* xr = up + (size_t)row * NUP;
    float4 v = *(const float4*)(xr + j);
    float p0 = 0.f, p1 = 0.f, p2 = 0.f;
    if (j >= 4) {
        float4 pv = *(const float4*)(xr + j - 4);
        p0 = pv.w; p1 = pv.z; p2 = pv.y;
    }
    float w0 = w[0], w1 = w[1], w2 = w[2], w3 = w[3];
    float o0 = w3 * v.x + w2 * p0 + w1 * p1 + w0 * p2;
    float o1 = w3 * v.y + w2 * v.x + w1 * p0 + w0 * p1;
    float o2 = w3 * v.z + w2 * v.y + w1 * v.x + w0 * p0;
    float o3 = w3 * v.w + w2 * v.z + w1 * v.y + w0 * v.x;
    o0 = o0 / (1.0f + expf(-o0));
    o1 = o1 / (1.0f + expf(-o1));
    o2 = o2 / (1.0f + expf(-o2));
    o3 = o3 / (1.0f + expf(-o3));
    __half h0, l0, h1, l1, h2, l2, h3, l3;
    split_f16(o0, h0, l0); split_f16(o1, h1, l1);
    split_f16(o2, h2, l2); split_f16(o3, h3, l3);
    __half* pr = p + (size_t)row * 2 * UPD;
    __half2 hv0 = __halves2half2(h0, h1), hv1 = __halves2half2(h2, h3);
    __half2 lv0 = __halves2half2(l0, l1), lv1 = __halves2half2(l2, l3);
    *(uint2*)(pr + j)       = make_uint2(*(uint32_t*)&hv0, *(uint32_t*)&hv1);
    *(uint2*)(pr + UPD + j) = make_uint2(*(uint32_t*)&lv0, *(uint32_t*)&lv1);
}

// -------------------- exact gate GEMM: i/f (16 cols) from xc hi+lo, fp32 -----------
#define GW_STRIDE 1538
#define GW_SMEM (16 * GW_STRIDE * 4)
__global__ __launch_bounds__(256) void gate_kernel(const __half* __restrict__ xcP,
                                                   const float* __restrict__ fW,
                                                   const float* __restrict__ fb,
                                                   float* __restrict__ gif) {
    extern __shared__ float ws[];   // [g][k], stride 1538
    for (int idx = threadIdx.x; idx < 16 * UPD; idx += 256) {
        int g = idx / UPD, k = idx % UPD;
        ws[g * GW_STRIDE + k] = fW[idx];
    }
    __syncthreads();
    int rowl = threadIdx.x >> 4, g = threadIdx.x & 15;
    int row = blockIdx.x * 16 + rowl;
    const __half* pr = xcP + (size_t)row * 2 * UPD;
    const float* wg = ws + g * GW_STRIDE;
    float acc = 0.f;
#pragma unroll 4
    for (int k = 0; k < UPD; k += 2) {
        __half2 h2 = *(const __half2*)(pr + k);
        __half2 l2 = *(const __half2*)(pr + UPD + k);
        float2 hf = __half22float2(h2), lf = __half22float2(l2);
        float2 w2 = *(const float2*)(wg + k);
        acc = fmaf(hf.x + lf.x, w2.x, acc);
        acc = fmaf(hf.y + lf.y, w2.y, acc);
    }
    acc += fb[g];
    gif[(size_t)row * 16 + g] = CAPV * tanhf(acc * (1.0f / CAPV));
}

// -------------------- sequential m-recurrence: ie/fe per (b,h,s) --------------------
__global__ __launch_bounds__(64) void mscan_kernel(const float* __restrict__ gif,
                                                   float* __restrict__ gie,
                                                   float* __restrict__ gfe,
                                                   float* __restrict__ outM) {
    int t = threadIdx.x;
    int b = t >> 3, h = t & 7;
    float m = 0.f;
    const float* base = gif + (size_t)b * SEQ * 16;
    float iv = base[h], fv = base[8 + h];
    for (int s = 0; s < SEQ; s++) {
        float i_t = iv, f_t = fv;
        if (s + 1 < SEQ) { iv = base[(s + 1) * 16 + h]; fv = base[(s + 1) * 16 + 8 + h]; }
        float m_t = fmaxf(f_t + m, i_t);
        float ie = expf(i_t - m_t);
        float fe = expf(f_t - m_t + m);
        m = m_t;
        size_t o = ((size_t)b * SEQ + s) * NH + h;
        gie[o] = ie; gfe[o] = fe;
    }
    outM[b * 8 + h] = m;
}

// -------------------- sequential mLSTM scan: 2 blocks per (b,h), e-split -------------
__global__ __launch_bounds__(96) void scan_kernel(const float* __restrict__ sf,
                                                  const float* __restrict__ gie,
                                                  const float* __restrict__ gfe,
                                                  float* __restrict__ ht0,
                                                  float* __restrict__ ht1,
                                                  float* __restrict__ dpo,
                                                  float* __restrict__ outC,
                                                  float* __restrict__ outN) {
    int bx = blockIdx.x;
    int bh = bx >> 1, sp = bx & 1;
    int b = bh >> 3, h = bh & 7;
    int e0 = sp * 48;
    int t = threadIdx.x;
    const float inv = rsqrtf((float)HD);

    ull C[24];
#pragma unroll
    for (int e = 0; e < 24; e++) C[e] = 0ull;
    float nd = 1.0f;

    __shared__ __align__(16) float qs[2][48];
    __shared__ __align__(16) float ks[2][48];

    const float* base = sf + (size_t)b * SEQ * NSF;
    const float* geb = gie + (size_t)b * SEQ * NH + h;
    const float* gfb = gfe + (size_t)b * SEQ * NH + h;
    float* htp = sp ? ht1 : ht0;

    float qv = 0.f, kv = 0.f;
    if (t < 48) {
        qv = base[OFF_Q + h * HD + e0 + t];
        kv = base[OFF_K + h * HD + e0 + t];
    }
    float vv = base[OFF_V + h * HD + t];
    float ie = geb[0], fe = gfb[0];

    for (int s = 0; s < SEQ; s++) {
        int p = s & 1;
        float qd = qv, kd = kv * inv, vd = vv;
        float iec = ie, fec = fe;
        if (t < 48) { qs[p][t] = qd; ks[p][t] = kd; }
        __syncthreads();

        if (s + 1 < SEQ) {
            const float* b2 = base + (size_t)(s + 1) * NSF;
            if (t < 48) {
                qv = b2[OFF_Q + h * HD + e0 + t];
                kv = b2[OFF_K + h * HD + e0 + t];
            }
            vv = b2[OFF_V + h * HD + t];
            ie = geb[(size_t)(s + 1) * NH];
            fe = gfb[(size_t)(s + 1) * NH];
        }

        ull pa  = bcast2(iec * vd);
        ull pfe = bcast2(fec);
        const ulonglong2* kp2 = (const ulonglong2*)ks[p];
        const ulonglong2* qp2 = (const ulonglong2*)qs[p];
        ull hn0 = 0ull, hn1 = 0ull, hn2a = 0ull, hn3 = 0ull;
#pragma unroll
        for (int e2 = 0; e2 < 12; e2 += 2) {
            ulonglong2 kk0 = kp2[e2],     qq0 = qp2[e2];
            ulonglong2 kk1 = kp2[e2 + 1], qq1 = qp2[e2 + 1];
            ull c;
            c = ffma2(pa, kk0.x, fmul2(pfe, C[2 * e2 + 0])); C[2 * e2 + 0] = c; hn0  = ffma2(c, qq0.x, hn0);
            c = ffma2(pa, kk0.y, fmul2(pfe, C[2 * e2 + 1])); C[2 * e2 + 1] = c; hn1  = ffma2(c, qq0.y, hn1);
            c = ffma2(pa, kk1.x, fmul2(pfe, C[2 * e2 + 2])); C[2 * e2 + 2] = c; hn2a = ffma2(c, qq1.x, hn2a);
            c = ffma2(pa, kk1.y, fmul2(pfe, C[2 * e2 + 3])); C[2 * e2 + 3] = c; hn3  = ffma2(c, qq1.y, hn3);
        }
        float2 hf = unpack2(fadd2(fadd2(hn0, hn1), fadd2(hn2a, hn3)));
        float hnv = hf.x + hf.y;

        size_t o = ((size_t)b * SEQ + s) * HID + h * HD;
        htp[o + t] = hnv;
        if (t < 48) {
            nd = fmaf(iec, kd, fec * nd);
            dpo[o + e0 + t] = nd * qd;
        }
    }

    float* Cr = outC + ((size_t)bh * HD + t) * HD + e0;
#pragma unroll
    for (int e = 0; e < 24; e++) {
        float2 f = unpack2(C[e]);
        *(float2*)(Cr + 2 * e) = f;
    }
    if (t < 48) outN[bh * HD + e0 + t] = nd;
}

// -------------------- denom reduce + o-gate, LN2, fp16 2-term A-pack ----------------
__global__ __launch_bounds__(256) void post_pack_kernel(const float* __restrict__ sf,
                                                        const float* __restrict__ ht0,
                                                        const float* __restrict__ ht1,
                                                        const float* __restrict__ dp,
                                                        const float* __restrict__ g,
                                                        const float* __restrict__ b,
                                                        __half* __restrict__ p) {
    __shared__ float sh[8], sh2[8], sden[8];
    int row = blockIdx.x, t = threadIdx.x;
    int w = t >> 5, lane = t & 31;

    const float* dpr = dp + (size_t)row * HID;
    float sdp = dpr[w * 96 + lane] + dpr[w * 96 + 32 + lane] + dpr[w * 96 + 64 + lane];
#pragma unroll
    for (int o = 16; o > 0; o >>= 1) sdp += __shfl_xor_sync(0xffffffffu, sdp, o);
    if (lane == 0) sden[w] = fmaxf(sdp, 1.0f);
    __syncthreads();

    const float* fr = sf + (size_t)row * NSF + OFF_O;
    const float* h0 = ht0 + (size_t)row * HID;
    const float* h1 = ht1 + (size_t)row * HID;
    float hv[3]; float s = 0.f, s2 = 0.f;
#pragma unroll
    for (int k = 0; k < 3; k++) {
        int j = t + k * 256;
        float oraw = fr[j];
        float og = 1.0f / (1.0f + expf(-CAPV * tanhf(oraw * (1.0f / CAPV))));
        float h = og * ((h0[j] + h1[j]) / sden[j / 96]);
        hv[k] = h; s += h; s2 += h * h;
    }
    block_reduce_sum2(s, s2, sh, sh2);
    float mean = s * (1.0f / HID);
    float var  = s2 * (1.0f / HID) - mean * mean;
    float r = rsqrtf(var + 1e-6f);
    __half* pr = p + (size_t)row * 2 * HID;
#pragma unroll
    for (int k = 0; k < 3; k++) {
        int j = t + k * 256;
        float y = (hv[k] - mean) * r * g[j] + b[j];
        __half hi, lo; split_f16(y, hi, lo);
        pr[j] = hi; pr[HID + j] = lo;
    }
}

// -------------------- final fuse: (y1 + xskip)*silu(rt) + x, float4 --------------------
__global__ __launch_bounds__(192) void final_kernel(const float* __restrict__ y1,
                                                    const float* __restrict__ sf,
                                                    const float* __restrict__ up,
                                                    const float* __restrict__ x,
                                                    float* __restrict__ out) {
    int row = blockIdx.x;
    int j = threadIdx.x * 4;
    float4 yv = *(const float4*)(y1 + (size_t)row * HID + j);
    float4 sk = *(const float4*)(sf + (size_t)row * NSF + j);
    float4 rv = *(const float4*)(up + (size_t)row * NUP + UPD + j);
    float4 xv = *(const float4*)(x + (size_t)row * HID + j);
    float4 o;
    o.x = (yv.x + sk.x) * (rv.x / (1.0f + expf(-rv.x))) + xv.x;
    o.y = (yv.y + sk.y) * (rv.y / (1.0f + expf(-rv.y))) + xv.y;
    o.z = (yv.z + sk.z) * (rv.z / (1.0f + expf(-rv.z))) + xv.z;
    o.w = (yv.w + sk.w) * (rv.w / (1.0f + expf(-rv.w))) + xv.w;
    *(float4*)(out + (size_t)row * HID + j) = o;
}

// -------------------- launch --------------------
#define GEMM_SMEM (3 * 32768)

extern "C" void kernel_launch(void* const* d_in, const int* in_sizes, int n_in,
                              void* d_out, int out_size) {
    (void)in_sizes; (void)n_in; (void)out_size;
    const float* x       = (const float*)d_in[0];
    const float* ln1_g   = (const float*)d_in[1];
    const float* ln1_b   = (const float*)d_in[2];
    const float* W_up_l  = (const float*)d_in[3];
    const float* W_up_r  = (const float*)d_in[4];
    const float* conv_w  = (const float*)d_in[5];
    const float* W_skip  = (const float*)d_in[6];
    const float* fused_W = (const float*)d_in[7];
    const float* fused_b = (const float*)d_in[8];
    const float* ln2_g   = (const float*)d_in[9];
    const float* ln2_b   = (const float*)d_in[10];
    const float* W_down  = (const float*)d_in[11];
    float* out = (float*)d_out;

    __nv_bfloat16 *xnP, *WupP;
    __half *xcP, *hn2P, *WsfP, *WdP;
    float *upM, *sfM, *ht0, *ht1, *dp, *y1, *biasM, *gif, *gie, *gfe;
    cudaGetSymbolAddress((void**)&xnP,   g_xnP);
    cudaGetSymbolAddress((void**)&xcP,   g_xcP);
    cudaGetSymbolAddress((void**)&hn2P,  g_hn2P);
    cudaGetSymbolAddress((void**)&WupP,  g_WupP);
    cudaGetSymbolAddress((void**)&WsfP,  g_WsfP);
    cudaGetSymbolAddress((void**)&WdP,   g_WdP);
    cudaGetSymbolAddress((void**)&upM,   g_upM);
    cudaGetSymbolAddress((void**)&sfM,   g_sfM);
    cudaGetSymbolAddress((void**)&ht0,   g_ht0);
    cudaGetSymbolAddress((void**)&ht1,   g_ht1);
    cudaGetSymbolAddress((void**)&dp,    g_dp);
    cudaGetSymbolAddress((void**)&y1,    g_y1);
    cudaGetSymbolAddress((void**)&biasM, g_biasM);
    cudaGetSymbolAddress((void**)&gif,   g_if);
    cudaGetSymbolAddress((void**)&gie,   g_ie);
    cudaGetSymbolAddress((void**)&gfe,   g_fe);

    cudaFuncSetAttribute(gemm_mma_kernel<0>, cudaFuncAttributeMaxDynamicSharedMemorySize, GEMM_SMEM);
    cudaFuncSetAttribute(gemm_mma_kernel<1>, cudaFuncAttributeMaxDynamicSharedMemorySize, GEMM_SMEM);
    cudaFuncSetAttribute(gate_kernel, cudaFuncAttributeMaxDynamicSharedMemorySize, GW_SMEM);

    // ordered so our launch #3 = up-GEMM (harness offset 2 -> ncu -s 5 profiles it)
    pack_b3_kernel<<<(UPD * INP + 255) / 256, 256>>>(W_up_l, WupP, INP, UPD * INP);            // 0
    pack_b3_kernel<<<(HID * INP + 255) / 256, 256>>>(W_up_r, WupP + (size_t)UPD * 3 * INP, INP, HID * INP); // 1
    ln1_pack_kernel<<<ROWS, 256>>>(x, ln1_g, ln1_b, xnP);                                     // 2
    gemm_mma_kernel<0><<<dim3(NUP / 128, ROWS / 128), 128, GEMM_SMEM>>>(NUP, 3 * INP, xnP, WupP, nullptr, upM); // 3

    conv_silu_pack_kernel<<<dim3(UPD / 512, ROWS), 128>>>(upM, conv_w, xcP);                  // 4
    pack_b2_kernel<<<(HID * UPD + 255) / 256, 256>>>(W_skip, WsfP, UPD, HID * UPD);           // 5
    pack_b2_kernel<<<(FOUT * UPD + 255) / 256, 256>>>(fused_W, WsfP + (size_t)HID * 2 * UPD, UPD, FOUT * UPD); // 6
    bias_build_kernel<<<(NSF + 255) / 256, 256>>>(fused_b, biasM);                            // 7

    gemm_mma_kernel<1><<<dim3((NSF + 127) / 128, ROWS / 128), 128, GEMM_SMEM>>>(NSF, 2 * UPD, xcP, WsfP, biasM, sfM); // 8

    gate_kernel<<<ROWS / 16, 256, GW_SMEM>>>(xcP, fused_W, fused_b, gif);                     // 9
    float* outC = out + (size_t)ROWS * INP;
    float* outN = outC + (size_t)BATCH * NH * HD * HD;
    float* outM = outN + (size_t)BATCH * NH * HD;
    mscan_kernel<<<1, 64>>>(gif, gie, gfe, outM);                                             // 10
    scan_kernel<<<BATCH * NH * 2, 96>>>(sfM, gie, gfe, ht0, ht1, dp, outC, outN);             // 11

    post_pack_kernel<<<ROWS, 256>>>(sfM, ht0, ht1, dp, ln2_g, ln2_b, hn2P);                   // 12
    pack_b2_kernel<<<(INP * HID + 255) / 256, 256>>>(W_down, WdP, HID, INP * HID);            // 13
    gemm_mma_kernel<1><<<dim3(HID / 128, ROWS / 128), 128, GEMM_SMEM>>>(HID, 2 * HID, hn2P, WdP, nullptr, y1); // 14

    final_kernel<<<ROWS, 192>>>(y1, sfM, upM, x, out);                                        // 15
}

// round 16
// speedup vs baseline: 2.6275x; 1.0884x over previous
#include <cuda_runtime.h>
#include <cuda_bf16.h>
#include <cuda_fp16.h>
#include <cstdint>

#define INP   768
#define HID   768
#define NH    8
#define HD    96
#define UPD   1536
#define FOUT  3088
#define BATCH 8
#define SEQ   1024
#define ROWS  (BATCH*SEQ)   /* 8192 */
#define CAPV  15.0f

#define NUP   (UPD + HID)          /* 2304 merged up-proj width  */
#define NSF   (HID + FOUT)         /* 3856 merged skip+fused width */
#define OFF_O (HID + 16)           /* 784  */
#define OFF_Q (HID + 784)          /* 1552 */
#define OFF_K (HID + 1552)         /* 2320 */
#define OFF_V (HID + 2320)         /* 3088 */

typedef unsigned long long ull;

// -------------------- scratch (no allocs allowed) --------------------
__device__ __align__(256) __nv_bfloat16 g_xnP  [ (size_t)ROWS*3*INP ];   // bf16 [hi|lo|hi]
__device__ __align__(256) __half        g_xcP  [ (size_t)ROWS*2*UPD ];   // fp16 [hi|lo]
__device__ __align__(256) __half        g_hn2P [ (size_t)ROWS*2*HID ];   // fp16 [hi|lo]
__device__ __align__(256) __nv_bfloat16 g_WupP [ (size_t)NUP*3*INP ];    // bf16 [hi|hi|lo]
__device__ __align__(256) __half        g_WsfP [ (size_t)NSF*2*UPD ];    // fp16 [hi|hi]
__device__ __align__(256) __half        g_WdP  [ (size_t)INP*2*HID ];    // fp16 [hi|hi]
__device__ __align__(256) float g_upM  [ (size_t)ROWS*NUP ];   // [xt | rt]
__device__ __align__(256) float g_sfM  [ (size_t)ROWS*NSF ];   // [xskip | fused]
__device__ __align__(256) float g_htB  [ (size_t)4*ROWS*HID ]; // 4 e-split partials
__device__ __align__(256) float g_dp   [ (size_t)ROWS*HID ];
__device__ __align__(256) float g_y1   [ (size_t)ROWS*HID ];
__device__ __align__(256) float g_biasM[ NSF ];
__device__ __align__(256) float g_if   [ (size_t)ROWS*16 ];   // soft-capped i(8)|f(8) per row
__device__ __align__(256) float g_ie   [ (size_t)ROWS*NH ];
__device__ __align__(256) float g_fe   [ (size_t)ROWS*NH ];

// -------------------- packed f32x2 helpers --------------------
__device__ __forceinline__ ull ffma2(ull a, ull b, ull c) {
    ull d; asm("fma.rn.f32x2 %0, %1, %2, %3;" : "=l"(d) : "l"(a), "l"(b), "l"(c)); return d;
}
__device__ __forceinline__ ull fmul2(ull a, ull b) {
    ull d; asm("mul.rn.f32x2 %0, %1, %2;" : "=l"(d) : "l"(a), "l"(b)); return d;
}
__device__ __forceinline__ ull fadd2(ull a, ull b) {
    ull d; asm("add.rn.f32x2 %0, %1, %2;" : "=l"(d) : "l"(a), "l"(b)); return d;
}
__device__ __forceinline__ ull bcast2(float x) {
    ull d; asm("mov.b64 %0, {%1, %1};" : "=l"(d) : "f"(x)); return d;
}
__device__ __forceinline__ float2 unpack2(ull v) {
    float2 f; asm("mov.b64 {%0, %1}, %2;" : "=f"(f.x), "=f"(f.y) : "l"(v)); return f;
}

// -------------------- mma / ldmatrix / cp.async helpers --------------------
static __device__ __forceinline__ uint32_t smem_u32(const void* p) {
    uint32_t a;
    asm("{ .reg .u64 t; cvta.to.shared.u64 t, %1; cvt.u32.u64 %0, t; }" : "=r"(a) : "l"(p));
    return a;
}
#define LDSM4(r, addr) \
    asm volatile("ldmatrix.sync.aligned.m8n8.x4.shared.b16 {%0,%1,%2,%3}, [%4];" \
        : "=r"((r)[0]), "=r"((r)[1]), "=r"((r)[2]), "=r"((r)[3]) : "r"(addr))
#define MMA_BF16(c, a, b0, b1) \
    asm volatile("mma.sync.aligned.m16n8k16.row.col.f32.bf16.bf16.f32 " \
        "{%0,%1,%2,%3}, {%4,%5,%6,%7}, {%8,%9}, {%0,%1,%2,%3};" \
        : "+f"((c)[0]), "+f"((c)[1]), "+f"((c)[2]), "+f"((c)[3]) \
        : "r"((a)[0]), "r"((a)[1]), "r"((a)[2]), "r"((a)[3]), "r"(b0), "r"(b1))
#define MMA_F16(c, a, b0, b1) \
    asm volatile("mma.sync.aligned.m16n8k16.row.col.f32.f16.f16.f32 " \
        "{%0,%1,%2,%3}, {%4,%5,%6,%7}, {%8,%9}, {%0,%1,%2,%3};" \
        : "+f"((c)[0]), "+f"((c)[1]), "+f"((c)[2]), "+f"((c)[3]) \
        : "r"((a)[0]), "r"((a)[1]), "r"((a)[2]), "r"((a)[3]), "r"(b0), "r"(b1))
static __device__ __forceinline__ void cp_async16(uint32_t d, const void* g, int sz) {
    asm volatile("cp.async.cg.shared.global [%0], [%1], 16, %2;"
                 :: "r"(d), "l"(g), "r"(sz) : "memory");
}
#define CP_COMMIT() asm volatile("cp.async.commit_group;" ::: "memory")
#define CP_WAIT1()  asm volatile("cp.async.wait_group 1;" ::: "memory")
#define CP_WAIT0()  asm volatile("cp.async.wait_group 0;" ::: "memory")

// 128B rows, 8 chunks of 16B, XOR-swizzled by row&7
static __device__ __forceinline__ uint32_t sw128(uint32_t base, int row, int ch) {
    return base + ((uint32_t)row << 7) + ((uint32_t)((ch ^ (row & 7)) & 7) << 4);
}

// -------------------- reduction helper --------------------
__device__ __forceinline__ void block_reduce_sum2(float& s, float& s2,
                                                  float* sh, float* sh2) {
    int lane = threadIdx.x & 31, wid = threadIdx.x >> 5;
#pragma unroll
    for (int o = 16; o > 0; o >>= 1) {
        s  += __shfl_xor_sync(0xffffffffu, s,  o);
        s2 += __shfl_xor_sync(0xffffffffu, s2, o);
    }
    if (lane == 0) { sh[wid] = s; sh2[wid] = s2; }
    __syncthreads();
    float t = 0.f, t2 = 0.f;
#pragma unroll
    for (int i = 0; i < 8; i++) { t += sh[i]; t2 += sh2[i]; }
    s = t; s2 = t2;
}

__device__ __forceinline__ void split_bf16(float x, __nv_bfloat16& hi, __nv_bfloat16& lo) {
    hi = __float2bfloat16(x);
    lo = __float2bfloat16(x - __bfloat162float(hi));
}
__device__ __forceinline__ void split_f16(float x, __half& hi, __half& lo) {
    hi = __float2half(x);
    lo = __float2half(x - __half2float(hi));
}

// -------------------- LayerNorm over 768 + bf16 3-term A-pack --------------------
__global__ __launch_bounds__(256) void ln1_pack_kernel(const float* __restrict__ x,
                                                       const float* __restrict__ g,
                                                       const float* __restrict__ b,
                                                       __nv_bfloat16* __restrict__ p) {
    __shared__ float sh[8], sh2[8];
    int row = blockIdx.x, t = threadIdx.x;
    const float* xr = x + (size_t)row * INP;
    float v0 = xr[t], v1 = xr[t + 256], v2 = xr[t + 512];
    float s = v0 + v1 + v2;
    float s2 = v0 * v0 + v1 * v1 + v2 * v2;
    block_reduce_sum2(s, s2, sh, sh2);
    float mean = s * (1.0f / INP);
    float var  = s2 * (1.0f / INP) - mean * mean;
    float r = rsqrtf(var + 1e-6f);
    __nv_bfloat16* pr = p + (size_t)row * 3 * INP;
#pragma unroll
    for (int k = 0; k < 3; k++) {
        int j = t + k * 256;
        float v = (k == 0) ? v0 : (k == 1) ? v1 : v2;
        float y = (v - mean) * r * g[j] + b[j];
        __nv_bfloat16 hi, lo; split_bf16(y, hi, lo);
        pr[j] = hi; pr[INP + j] = lo; pr[2 * INP + j] = hi;
    }
}

// -------------------- weight packs --------------------
__global__ void pack_b3_kernel(const float* __restrict__ src,
                               __nv_bfloat16* __restrict__ dst,
                               int K, int total) {         // bf16 [hi|hi|lo]
    int i = blockIdx.x * blockDim.x + threadIdx.x;
    if (i >= total) return;
    int row = i / K, j = i % K;
    __nv_bfloat16 hi, lo; split_bf16(src[i], hi, lo);
    __nv_bfloat16* d = dst + (size_t)row * 3 * K;
    d[j] = hi; d[K + j] = hi; d[2 * K + j] = lo;
}
__global__ void pack_b2_kernel(const float* __restrict__ src,
                               __half* __restrict__ dst,
                               int K, int total) {         // fp16 [hi|hi]
    int i = blockIdx.x * blockDim.x + threadIdx.x;
    if (i >= total) return;
    int row = i / K, j = i % K;
    __half hi = __float2half(src[i]);
    __half* d = dst + (size_t)row * 2 * K;
    d[j] = hi; d[K + j] = hi;
}

__global__ void bias_build_kernel(const float* __restrict__ fb, float* __restrict__ bm) {
    int i = blockIdx.x * blockDim.x + threadIdx.x;
    if (i >= NSF) return;
    bm[i] = (i < HID) ? 0.f : fb[i - HID];
}

// -------------------- warp-MMA NT GEMM, K64 tiles, 3-stage cp.async ------------
// 128 thr = 4 warps (2x2); block tile 128x128; warp tile 64x64; dyn smem 96KB.
template<int FP16>
__global__ __launch_bounds__(128) void gemm_mma_kernel(
    int Nn, int Kp,
    const void* __restrict__ Av, const void* __restrict__ Bv,
    const float* __restrict__ bias, float* __restrict__ Cout) {
    const __half* A = (const __half*)Av;      // 16-bit payload; dtype via FP16 flag
    const __half* B = (const __half*)Bv;
    extern __shared__ __align__(1024) char sm[];
    uint32_t sA = smem_u32(sm);            // 3 x 16KB
    uint32_t sB = sA + 49152u;             // 3 x 16KB
    int tid = threadIdx.x;
    int bm = blockIdx.y * 128, bn = blockIdx.x * 128;
    int wid = tid >> 5, lane = tid & 31;
    int wm = wid >> 1, wn = wid & 1;
    int lr = lane & 7, grp = lane >> 3;
    int niter = Kp >> 6;

    float acc[4][8][4];
#pragma unroll
    for (int i = 0; i < 4; i++)
#pragma unroll
        for (int j = 0; j < 8; j++)
#pragma unroll
            for (int q = 0; q < 4; q++) acc[i][j][q] = 0.f;

    auto issue_stage = [&](int it, int s) {
        int kt = it << 6;
#pragma unroll
        for (int q = 0; q < 8; q++) {
            int idx = tid + q * 128;
            int r = idx >> 3, ch = idx & 7;
            cp_async16(sw128(sA + (uint32_t)s * 16384u, r, ch),
                       A + (size_t)(bm + r) * Kp + kt + ch * 8, 16);
        }
#pragma unroll
        for (int q = 0; q < 8; q++) {
            int idx = tid + q * 128;
            int r = idx >> 3, ch = idx & 7;
            int br = bn + r;
            cp_async16(sw128(sB + (uint32_t)s * 16384u, r, ch),
                       B + (size_t)(br < Nn ? br : 0) * Kp + kt + ch * 8,
                       br < Nn ? 16 : 0);
        }
        CP_COMMIT();
    };

    issue_stage(0, 0);
    if (niter > 1) issue_stage(1, 1);

    for (int it = 0; it < niter; it++) {
        int s = it % 3;
        if (it + 1 < niter) CP_WAIT1(); else CP_WAIT0();
        __syncthreads();

        uint32_t Ab = sA + (uint32_t)s * 16384u;
        uint32_t Bb = sB + (uint32_t)s * 16384u;
#pragma unroll
        for (int ks = 0; ks < 4; ks++) {
            uint32_t a[4][4];
#pragma unroll
            for (int fm = 0; fm < 4; fm++) {
                int row = wm * 64 + fm * 16 + lr + ((grp & 1) << 3);
                int ch = ks * 2 + (grp >> 1);
                LDSM4(a[fm], sw128(Ab, row, ch));
            }
            uint32_t b[4][4];
#pragma unroll
            for (int np = 0; np < 4; np++) {
                int row = wn * 64 + np * 16 + lr + ((grp >> 1) << 3);
                int ch = ks * 2 + (grp & 1);
                LDSM4(b[np], sw128(Bb, row, ch));
            }
#pragma unroll
            for (int fm = 0; fm < 4; fm++)
#pragma unroll
                for (int np = 0; np < 4; np++) {
#pragma unroll
                    for (int fl = 0; fl < 2; fl++) {
                        if (FP16) { MMA_F16(acc[fm][np * 2 + fl], a[fm], b[np][fl * 2], b[np][fl * 2 + 1]); }
                        else      { MMA_BF16(acc[fm][np * 2 + fl], a[fm], b[np][fl * 2], b[np][fl * 2 + 1]); }
                    }
                }
        }
        if (it + 2 < niter) issue_stage(it + 2, (it + 2) % 3);
    }

    int qr = lane >> 2, qc = lane & 3;
#pragma unroll
    for (int fn = 0; fn < 8; fn++) {
        int np = fn >> 1, fl = fn & 1;
        int col = bn + wn * 64 + np * 16 + fl * 8 + qc * 2;
        if (col < Nn) {
            float bx = bias ? bias[col] : 0.f;
            float by = bias ? bias[col + 1] : 0.f;
#pragma unroll
            for (int fm = 0; fm < 4; fm++) {
                int row0 = bm + wm * 64 + fm * 16 + qr;
                float2 v0 = make_float2(acc[fm][fn][0] + bx, acc[fm][fn][1] + by);
                float2 v1 = make_float2(acc[fm][fn][2] + bx, acc[fm][fn][3] + by);
                *(float2*)(Cout + (size_t)row0 * Nn + col) = v0;
                *(float2*)(Cout + (size_t)(row0 + 8) * Nn + col) = v1;
            }
        }
    }
}

// -------------------- causal conv + silu + fp16 2-term A-pack, float4/thread ---------
__global__ __launch_bounds__(128) void conv_silu_pack_kernel(const float* __restrict__ up,
                                                             const float* __restrict__ w,
                                                             __half* __restrict__ p) {
    int row = blockIdx.y;
    int j = (blockIdx.x * 128 + threadIdx.x) * 4;
    const float* xr = up + (size_t)row * NUP;
    float4 v = *(const float4*)(xr + j);
    float p0 = 0.f, p1 = 0.f, p2 = 0.f;
    if (j >= 4) {
        float4 pv = *(const float4*)(xr + j - 4);
        p0 = pv.w; p1 = pv.z; p2 = pv.y;
    }
    float w0 = w[0], w1 = w[1], w2 = w[2], w3 = w[3];
    float o0 = w3 * v.x + w2 * p0 + w1 * p1 + w0 * p2;
    float o1 = w3 * v.y + w2 * v.x + w1 * p0 + w0 * p1;
    float o2 = w3 * v.z + w2 * v.y + w1 * v.x + w0 * p0;
    float o3 = w3 * v.w + w2 * v.z + w1 * v.y + w0 * v.x;
    o0 = o0 / (1.0f + expf(-o0));
    o1 = o1 / (1.0f + expf(-o1));
    o2 = o2 / (1.0f + expf(-o2));
    o3 = o3 / (1.0f + expf(-o3));
    __half h0, l0, h1, l1, h2, l2, h3, l3;
    split_f16(o0, h0, l0); split_f16(o1, h1, l1);
    split_f16(o2, h2, l2); split_f16(o3, h3, l3);
    __half* pr = p + (size_t)row * 2 * UPD;
    __half2 hv0 = __halves2half2(h0, h1), hv1 = __halves2half2(h2, h3);
    __half2 lv0 = __halves2half2(l0, l1), lv1 = __halves2half2(l2, l3);
    *(uint2*)(pr + j)       = make_uint2(*(uint32_t*)&hv0, *(uint32_t*)&hv1);
    *(uint2*)(pr + UPD + j) = make_uint2(*(uint32_t*)&lv0, *(uint32_t*)&lv1);
}

// -------------------- exact gate GEMM: i/f (16 cols) from xc hi+lo, fp32 -----------
#define GW_STRIDE 1538
#define GW_SMEM (16 * GW_STRIDE * 4)
__global__ __launch_bounds__(256) void gate_kernel(const __half* __restrict__ xcP,
                                                   const float* __restrict__ fW,
                                                   const float* __restrict__ fb,
                                                   float* __restrict__ gif) {
    extern __shared__ float ws[];   // [g][k], stride 1538
    for (int idx = threadIdx.x; idx < 16 * UPD; idx += 256) {
        int g = idx / UPD, k = idx % UPD;
        ws[g * GW_STRIDE + k] = fW[idx];
    }
    __syncthreads();
    int rowl = threadIdx.x >> 4, g = threadIdx.x & 15;
    int row = blockIdx.x * 16 + rowl;
    const __half* pr = xcP + (size_t)row * 2 * UPD;
    const float* wg = ws + g * GW_STRIDE;
    float acc = 0.f;
#pragma unroll 4
    for (int k = 0; k < UPD; k += 2) {
        __half2 h2 = *(const __half2*)(pr + k);
        __half2 l2 = *(const __half2*)(pr + UPD + k);
        float2 hf = __half22float2(h2), lf = __half22float2(l2);
        float2 w2 = *(const float2*)(wg + k);
        acc = fmaf(hf.x + lf.x, w2.x, acc);
        acc = fmaf(hf.y + lf.y, w2.y, acc);
    }
    acc += fb[g];
    gif[(size_t)row * 16 + g] = CAPV * tanhf(acc * (1.0f / CAPV));
}

// -------------------- parallel max-plus scan: ie/fe per (b,h,s) --------------------
// m_t = max(f_t + m_{t-1}, i_t); segment composition (F1,I1)∘(F2,I2) = (F1+F2, max(I1+F2, I2)).
// One block per (b,h), 1024 threads, Hillis-Steele in fp64.
__global__ __launch_bounds__(SEQ) void mscan_kernel(const float* __restrict__ gif,
                                                    float* __restrict__ gie,
                                                    float* __restrict__ gfe,
                                                    float* __restrict__ outM) {
    __shared__ double Fs[SEQ];
    __shared__ double Is[SEQ];
    int bh = blockIdx.x;
    int b = bh >> 3, h = bh & 7;
    int s = threadIdx.x;
    const float* base = gif + (size_t)b * SEQ * 16;
    float fi = base[s * 16 + h];        // i_t
    float ff = base[s * 16 + 8 + h];    // f_t
    double F = (double)ff, I = (double)fi;
    Fs[s] = F; Is[s] = I;
    __syncthreads();
#pragma unroll
    for (int off = 1; off < SEQ; off <<= 1) {
        double Fn = F, In = I;
        if (s >= off) {
            double F1 = Fs[s - off], I1 = Is[s - off];
            Fn = F1 + F;
            In = fmax(I1 + F, I);
        }
        __syncthreads();
        Fs[s] = Fn; Is[s] = In; F = Fn; I = In;
        __syncthreads();
    }
    double M = fmax(F, I);                       // m_s (m_0 = 0)
    double Mprev = (s > 0) ? fmax(Fs[s - 1], Is[s - 1]) : 0.0;
    size_t o = ((size_t)b * SEQ + s) * NH + h;
    gie[o] = expf((float)((double)fi - M));
    gfe[o] = expf((float)((double)ff - M + Mprev));
    if (s == SEQ - 1) outM[bh] = (float)M;
}

// -------------------- sequential mLSTM scan: 4 blocks per (b,h), e-split x4 ---------
__global__ __launch_bounds__(96) void scan_kernel(const float* __restrict__ sf,
                                                  const float* __restrict__ gie,
                                                  const float* __restrict__ gfe,
                                                  float* __restrict__ htB,
                                                  float* __restrict__ dpo,
                                                  float* __restrict__ outC,
                                                  float* __restrict__ outN) {
    int bx = blockIdx.x;
    int bh = bx >> 2, sp = bx & 3;
    int b = bh >> 3, h = bh & 7;
    int e0 = sp * 24;
    int t = threadIdx.x;
    const float inv = rsqrtf((float)HD);

    ull C[12];
#pragma unroll
    for (int e = 0; e < 12; e++) C[e] = 0ull;
    float nd = 1.0f;

    __shared__ __align__(16) float qs[2][24];
    __shared__ __align__(16) float ks[2][24];

    const float* base = sf + (size_t)b * SEQ * NSF;
    const float* geb = gie + (size_t)b * SEQ * NH + h;
    const float* gfb = gfe + (size_t)b * SEQ * NH + h;
    float* htp = htB + (size_t)sp * ROWS * HID;

    float qv = 0.f, kv = 0.f;
    if (t < 24) {
        qv = base[OFF_Q + h * HD + e0 + t];
        kv = base[OFF_K + h * HD + e0 + t];
    }
    float vv = base[OFF_V + h * HD + t];
    float ie = geb[0], fe = gfb[0];

    for (int s = 0; s < SEQ; s++) {
        int p = s & 1;
        float qd = qv, kd = kv * inv, vd = vv;
        float iec = ie, fec = fe;
        if (t < 24) { qs[p][t] = qd; ks[p][t] = kd; }
        __syncthreads();

        if (s + 1 < SEQ) {
            const float* b2 = base + (size_t)(s + 1) * NSF;
            if (t < 24) {
                qv = b2[OFF_Q + h * HD + e0 + t];
                kv = b2[OFF_K + h * HD + e0 + t];
            }
            vv = b2[OFF_V + h * HD + t];
            ie = geb[(size_t)(s + 1) * NH];
            fe = gfb[(size_t)(s + 1) * NH];
        }

        ull pa  = bcast2(iec * vd);
        ull pfe = bcast2(fec);
        const ulonglong2* kp2 = (const ulonglong2*)ks[p];
        const ulonglong2* qp2 = (const ulonglong2*)qs[p];
        ull hn0 = 0ull, hn1 = 0ull, hn2a = 0ull, hn3 = 0ull;
#pragma unroll
        for (int e2 = 0; e2 < 6; e2 += 2) {
            ulonglong2 kk0 = kp2[e2],     qq0 = qp2[e2];
            ulonglong2 kk1 = kp2[e2 + 1], qq1 = qp2[e2 + 1];
            ull c;
            c = ffma2(pa, kk0.x, fmul2(pfe, C[2 * e2 + 0])); C[2 * e2 + 0] = c; hn0  = ffma2(c, qq0.x, hn0);
            c = ffma2(pa, kk0.y, fmul2(pfe, C[2 * e2 + 1])); C[2 * e2 + 1] = c; hn1  = ffma2(c, qq0.y, hn1);
            c = ffma2(pa, kk1.x, fmul2(pfe, C[2 * e2 + 2])); C[2 * e2 + 2] = c; hn2a = ffma2(c, qq1.x, hn2a);
            c = ffma2(pa, kk1.y, fmul2(pfe, C[2 * e2 + 3])); C[2 * e2 + 3] = c; hn3  = ffma2(c, qq1.y, hn3);
        }
        float2 hf = unpack2(fadd2(fadd2(hn0, hn1), fadd2(hn2a, hn3)));
        float hnv = hf.x + hf.y;

        size_t o = ((size_t)b * SEQ + s) * HID + h * HD;
        htp[o + t] = hnv;
        if (t < 24) {
            nd = fmaf(iec, kd, fec * nd);
            dpo[o + e0 + t] = nd * qd;
        }
    }

    float* Cr = outC + ((size_t)bh * HD + t) * HD + e0;
#pragma unroll
    for (int e = 0; e < 12; e++) {
        float2 f = unpack2(C[e]);
        *(float2*)(Cr + 2 * e) = f;
    }
    if (t < 24) outN[bh * HD + e0 + t] = nd;
}

// -------------------- denom reduce + o-gate, LN2, fp16 2-term A-pack ----------------
__global__ __launch_bounds__(256) void post_pack_kernel(const float* __restrict__ sf,
                                                        const float* __restrict__ htB,
                                                        const float* __restrict__ dp,
                                                        const float* __restrict__ g,
                                                        const float* __restrict__ b,
                                                        __half* __restrict__ p) {
    __shared__ float sh[8], sh2[8], sden[8];
    int row = blockIdx.x, t = threadIdx.x;
    int w = t >> 5, lane = t & 31;

    const float* dpr = dp + (size_t)row * HID;
    float sdp = dpr[w * 96 + lane] + dpr[w * 96 + 32 + lane] + dpr[w * 96 + 64 + lane];
#pragma unroll
    for (int o = 16; o > 0; o >>= 1) sdp += __shfl_xor_sync(0xffffffffu, sdp, o);
    if (lane == 0) sden[w] = fmaxf(sdp, 1.0f);
    __syncthreads();

    const float* fr = sf + (size_t)row * NSF + OFF_O;
    const float* h0 = htB + (size_t)row * HID;
    const float* h1 = h0 + (size_t)ROWS * HID;
    const float* h2 = h1 + (size_t)ROWS * HID;
    const float* h3 = h2 + (size_t)ROWS * HID;
    float hv[3]; float s = 0.f, s2 = 0.f;
#pragma unroll
    for (int k = 0; k < 3; k++) {
        int j = t + k * 256;
        float oraw = fr[j];
        float og = 1.0f / (1.0f + expf(-CAPV * tanhf(oraw * (1.0f / CAPV))));
        float h = og * (((h0[j] + h1[j]) + (h2[j] + h3[j])) / sden[j / 96]);
        hv[k] = h; s += h; s2 += h * h;
    }
    block_reduce_sum2(s, s2, sh, sh2);
    float mean = s * (1.0f / HID);
    float var  = s2 * (1.0f / HID) - mean * mean;
    float r = rsqrtf(var + 1e-6f);
    __half* pr = p + (size_t)row * 2 * HID;
#pragma unroll
    for (int k = 0; k < 3; k++) {
        int j = t + k * 256;
        float y = (hv[k] - mean) * r * g[j] + b[j];
        __half hi, lo; split_f16(y, hi, lo);
        pr[j] = hi; pr[HID + j] = lo;
    }
}

// -------------------- final fuse: (y1 + xskip)*silu(rt) + x, float4 --------------------
__global__ __launch_bounds__(192) void final_kernel(const float* __restrict__ y1,
                                                    const float* __restrict__ sf,
                                                    const float* __restrict__ up,
                                                    const float* __restrict__ x,
                                                    float* __restrict__ out) {
    int row = blockIdx.x;
    int j = threadIdx.x * 4;
    float4 yv = *(const float4*)(y1 + (size_t)row * HID + j);
    float4 sk = *(const float4*)(sf + (size_t)row * NSF + j);
    float4 rv = *(const float4*)(up + (size_t)row * NUP + UPD + j);
    float4 xv = *(const float4*)(x + (size_t)row * HID + j);
    float4 o;
    o.x = (yv.x + sk.x) * (rv.x / (1.0f + expf(-rv.x))) + xv.x;
    o.y = (yv.y + sk.y) * (rv.y / (1.0f + expf(-rv.y))) + xv.y;
    o.z = (yv.z + sk.z) * (rv.z / (1.0f + expf(-rv.z))) + xv.z;
    o.w = (yv.w + sk.w) * (rv.w / (1.0f + expf(-rv.w))) + xv.w;
    *(float4*)(out + (size_t)row * HID + j) = o;
}

// -------------------- launch --------------------
#define GEMM_SMEM (3 * 32768)

extern "C" void kernel_launch(void* const* d_in, const int* in_sizes, int n_in,
                              void* d_out, int out_size) {
    (void)in_sizes; (void)n_in; (void)out_size;
    const float* x       = (const float*)d_in[0];
    const float* ln1_g   = (const float*)d_in[1];
    const float* ln1_b   = (const float*)d_in[2];
    const float* W_up_l  = (const float*)d_in[3];
    const float* W_up_r  = (const float*)d_in[4];
    const float* conv_w  = (const float*)d_in[5];
    const float* W_skip  = (const float*)d_in[6];
    const float* fused_W = (const float*)d_in[7];
    const float* fused_b = (const float*)d_in[8];
    const float* ln2_g   = (const float*)d_in[9];
    const float* ln2_b   = (const float*)d_in[10];
    const float* W_down  = (const float*)d_in[11];
    float* out = (float*)d_out;

    __nv_bfloat16 *xnP, *WupP;
    __half *xcP, *hn2P, *WsfP, *WdP;
    float *upM, *sfM, *htB, *dp, *y1, *biasM, *gif, *gie, *gfe;
    cudaGetSymbolAddress((void**)&xnP,   g_xnP);
    cudaGetSymbolAddress((void**)&xcP,   g_xcP);
    cudaGetSymbolAddress((void**)&hn2P,  g_hn2P);
    cudaGetSymbolAddress((void**)&WupP,  g_WupP);
    cudaGetSymbolAddress((void**)&WsfP,  g_WsfP);
    cudaGetSymbolAddress((void**)&WdP,   g_WdP);
    cudaGetSymbolAddress((void**)&upM,   g_upM);
    cudaGetSymbolAddress((void**)&sfM,   g_sfM);
    cudaGetSymbolAddress((void**)&htB,   g_htB);
    cudaGetSymbolAddress((void**)&dp,    g_dp);
    cudaGetSymbolAddress((void**)&y1,    g_y1);
    cudaGetSymbolAddress((void**)&biasM, g_biasM);
    cudaGetSymbolAddress((void**)&gif,   g_if);
    cudaGetSymbolAddress((void**)&gie,   g_ie);
    cudaGetSymbolAddress((void**)&gfe,   g_fe);

    cudaFuncSetAttribute(gemm_mma_kernel<0>, cudaFuncAttributeMaxDynamicSharedMemorySize, GEMM_SMEM);
    cudaFuncSetAttribute(gemm_mma_kernel<1>, cudaFuncAttributeMaxDynamicSharedMemorySize, GEMM_SMEM);
    cudaFuncSetAttribute(gate_kernel, cudaFuncAttributeMaxDynamicSharedMemorySize, GW_SMEM);

    // ordered so our launch #3 = up-GEMM (harness offset 2 -> ncu -s 5 profiles it)
    pack_b3_kernel<<<(UPD * INP + 255) / 256, 256>>>(W_up_l, WupP, INP, UPD * INP);            // 0
    pack_b3_kernel<<<(HID * INP + 255) / 256, 256>>>(W_up_r, WupP + (size_t)UPD * 3 * INP, INP, HID * INP); // 1
    ln1_pack_kernel<<<ROWS, 256>>>(x, ln1_g, ln1_b, xnP);                                     // 2
    gemm_mma_kernel<0><<<dim3(NUP / 128, ROWS / 128), 128, GEMM_SMEM>>>(NUP, 3 * INP, xnP, WupP, nullptr, upM); // 3

    conv_silu_pack_kernel<<<dim3(UPD / 512, ROWS), 128>>>(upM, conv_w, xcP);                  // 4
    pack_b2_kernel<<<(HID * UPD + 255) / 256, 256>>>(W_skip, WsfP, UPD, HID * UPD);           // 5
    pack_b2_kernel<<<(FOUT * UPD + 255) / 256, 256>>>(fused_W, WsfP + (size_t)HID * 2 * UPD, UPD, FOUT * UPD); // 6
    bias_build_kernel<<<(NSF + 255) / 256, 256>>>(fused_b, biasM);                            // 7

    gemm_mma_kernel<1><<<dim3((NSF + 127) / 128, ROWS / 128), 128, GEMM_SMEM>>>(NSF, 2 * UPD, xcP, WsfP, biasM, sfM); // 8

    gate_kernel<<<ROWS / 16, 256, GW_SMEM>>>(xcP, fused_W, fused_b, gif);                     // 9
    float* outC = out + (size_t)ROWS * INP;
    float* outN = outC + (size_t)BATCH * NH * HD * HD;
    float* outM = outN + (size_t)BATCH * NH * HD;
    mscan_kernel<<<BATCH * NH, SEQ>>>(gif, gie, gfe, outM);                                   // 10
    scan_kernel<<<BATCH * NH * 4, 96>>>(sfM, gie, gfe, htB, dp, outC, outN);                  // 11

    post_pack_kernel<<<ROWS, 256>>>(sfM, htB, dp, ln2_g, ln2_b, hn2P);                        // 12
    pack_b2_kernel<<<(INP * HID + 255) / 256, 256>>>(W_down, WdP, HID, INP * HID);            // 13
    gemm_mma_kernel<1><<<dim3(HID / 128, ROWS / 128), 128, GEMM_SMEM>>>(HID, 2 * HID, hn2P, WdP, nullptr, y1); // 14

    final_kernel<<<ROWS, 192>>>(y1, sfM, upM, x, out);                                        // 15
}